// round 8
// baseline (speedup 1.0000x reference)
#include <cuda_runtime.h>
#include <cuda_bf16.h>
#include <cstdint>

// ---------------------------------------------------------------------------
// ESN_2D: B=256, H=W=32, n=128, alpha^2=25, START_T=1
//  Phase A: persistent wavefront, ONE barrier per cell (warp-private l-state,
//           parity-double-buffered reduction buffer)
//  Phase B: feat (bf16 hi/lo features) + mma.sync bf16-split Gram
//  Phase C: out-of-smem blocked Cholesky + blocked substitutions
// ---------------------------------------------------------------------------

#define GSTRIDE 66564  // 258*258

__device__ float g_S[(size_t)1024 * 256 * 128];
__device__ float g_G[(size_t)256 * GSTRIDE];
__device__ unsigned short g_Fhi[(size_t)256 * 256 * 1024];
__device__ unsigned short g_Flo[(size_t)256 * 256 * 1024];

// ---- packed f32x2 helpers ----
__device__ __forceinline__ unsigned long long splat2(float x) {
    unsigned long long r;
    asm("mov.b64 %0, {%1, %1};" : "=l"(r) : "f"(x));
    return r;
}
__device__ __forceinline__ void fma2(unsigned long long &c, unsigned long long a,
                                     unsigned long long b) {
    asm("fma.rn.f32x2 %0, %1, %2, %0;" : "+l"(c) : "l"(a), "l"(b));
}
__device__ __forceinline__ float2 unpk(unsigned long long v) {
    float2 f;
    asm("mov.b64 {%0, %1}, %2;" : "=f"(f.x), "=f"(f.y) : "l"(v));
    return f;
}

// ---- cp.async helpers ----
__device__ __forceinline__ uint32_t smem_u32(const void* p) {
    uint32_t a;
    asm("{ .reg .u64 t; cvta.to.shared.u64 t, %1; cvt.u32.u64 %0, t; }" : "=r"(a) : "l"(p));
    return a;
}
__device__ __forceinline__ void cpasync16(uint32_t dst, const void* src) {
    asm volatile("cp.async.cg.shared.global [%0], [%1], 16;" :: "r"(dst), "l"(src) : "memory");
}
__device__ __forceinline__ void cpasync_commit() {
    asm volatile("cp.async.commit_group;" ::: "memory");
}
__device__ __forceinline__ void cpasync_wait0() {
    asm volatile("cp.async.wait_group 0;" ::: "memory");
}

// ---- bf16 mma.sync ----
__device__ __forceinline__ void mma16816(float* d, const uint32_t* a, const uint32_t* b) {
    asm volatile(
        "mma.sync.aligned.m16n8k16.row.col.f32.bf16.bf16.f32 "
        "{%0,%1,%2,%3}, {%4,%5,%6,%7}, {%8,%9}, {%0,%1,%2,%3};"
        : "+f"(d[0]), "+f"(d[1]), "+f"(d[2]), "+f"(d[3])
        : "r"(a[0]), "r"(a[1]), "r"(a[2]), "r"(a[3]), "r"(b[0]), "r"(b[1]));
}

// ---------------------------------------------------------------------------
// Phase A: persistent recurrence, 128 CTAs (2 batches each), 256 threads.
// One __syncthreads per cell. Warp w (jg = w>>1) keeps its own l-slice in
// lpriv[w]; red is parity-double-buffered; rowbuf slices are per-jg private
// (twin warps write identical values - benign). g_S stores split by warp parity.
// ---------------------------------------------------------------------------
__global__ void __launch_bounds__(256) esn_persist(const float* __restrict__ img,
                                                   const float* __restrict__ win,
                                                   const float* __restrict__ W1,
                                                   const float* __restrict__ W2)
{
    int b0 = blockIdx.x * 2;
    int t = threadIdx.x;
    int ip = t & 63;
    int jg = t >> 6;
    int wid = t >> 5;
    int lane = t & 31;

    unsigned long long w1r[32], w2r[32];
#pragma unroll
    for (int m = 0; m < 32; ++m) {
        int j = jg * 32 + m;
        w1r[m] = *(const unsigned long long*)&W1[j * 128 + ip * 2];
        w2r[m] = *(const unsigned long long*)&W2[j * 128 + ip * 2];
    }

    __shared__ float rowbuf[2][32][128];   // 32KB: prev-row states
    __shared__ float red[2][4][2][128];    // 8KB: parity-buffered partials
    __shared__ float lpriv[8][2][32];      // 2KB: per-warp left-state slices

    for (int idx = t; idx < 2 * 32 * 128; idx += 256)
        ((float*)rowbuf)[idx] = 0.f;
    __syncthreads();

    int jglob = jg * 32 + lane;
    float winp = win[jglob];
    const float* imgb0 = img + b0 * 1024;
    const float* imgb1 = img + (b0 + 1) * 1024;

    for (int h = 0; h < 32; ++h) {
        lpriv[wid][0][lane] = 0.f;
        lpriv[wid][1][lane] = 0.f;
        __syncwarp();
        for (int w = 0; w < 32; ++w) {
            int p = w & 1;
#pragma unroll
            for (int g = 0; g < 2; ++g) {
                unsigned long long accA = 0ull, accB = 0ull;
                const float* lb = &lpriv[wid][g][0];
                const float* ub = &rowbuf[g][w][jg * 32];
#pragma unroll
                for (int m4 = 0; m4 < 8; ++m4) {
                    float4 lv = *(const float4*)&lb[m4 * 4];
                    float4 uv = *(const float4*)&ub[m4 * 4];
                    fma2(accA, splat2(lv.x), w1r[m4 * 4 + 0]);
                    fma2(accB, splat2(uv.x), w2r[m4 * 4 + 0]);
                    fma2(accA, splat2(lv.y), w1r[m4 * 4 + 1]);
                    fma2(accB, splat2(uv.y), w2r[m4 * 4 + 1]);
                    fma2(accA, splat2(lv.z), w1r[m4 * 4 + 2]);
                    fma2(accB, splat2(uv.z), w2r[m4 * 4 + 2]);
                    fma2(accA, splat2(lv.w), w1r[m4 * 4 + 3]);
                    fma2(accB, splat2(uv.w), w2r[m4 * 4 + 3]);
                }
                float2 a = unpk(accA), bb = unpk(accB);
                *(float2*)&red[p][jg][g][ip * 2] = make_float2(a.x + bb.x, a.y + bb.y);
            }
            __syncthreads();
            // tail: each warp redundantly produces the 64 l-values it needs
            {
                int cell = h * 32 + w;
                float x0 = imgb0[cell];
                float x1 = imgb1[cell];
                float s0 = (red[p][0][0][jglob] + red[p][1][0][jglob]) +
                           (red[p][2][0][jglob] + red[p][3][0][jglob]);
                float s1 = (red[p][0][1][jglob] + red[p][1][1][jglob]) +
                           (red[p][2][1][jglob] + red[p][3][1][jglob]);
                float v0 = tanhf(fmaf(x0, winp, s0));
                float v1 = tanhf(fmaf(x1, winp, s1));
                lpriv[wid][0][lane] = v0;
                lpriv[wid][1][lane] = v1;
                rowbuf[0][w][jglob] = v0;
                rowbuf[1][w][jglob] = v1;
                if ((wid & 1) == 0)
                    g_S[(size_t)cell * 32768 + (size_t)b0 * 128 + jglob] = v0;
                else
                    g_S[(size_t)cell * 32768 + (size_t)(b0 + 1) * 128 + jglob] = v1;
                __syncwarp();
            }
        }
    }
}

// ---------------------------------------------------------------------------
// feat kernel (unchanged)
// ---------------------------------------------------------------------------
__global__ void __launch_bounds__(256) feat_kernel(const float* __restrict__ img)
{
    int b = blockIdx.x;
    int d = threadIdx.x;
    bool isLeft = d < 128;
    int dd = d & 127;

    float sumF = 0.f, sumUF = 0.f, su = 0.f;
    int hh = 0, ww = 0;

    uint4* outHi = (uint4*)&g_Fhi[((size_t)b * 256 + d) * 1024];
    uint4* outLo = (uint4*)&g_Flo[((size_t)b * 256 + d) * 1024];

    for (int sg = 0; sg < 128; ++sg) {
        unsigned short h8[8], l8[8];
#pragma unroll
        for (int j = 0; j < 8; ++j) {
            int s = sg * 8 + j;
            float f = 0.f, u = 0.f;
            if (s < 961) {
                int cell_l = (hh + 1) * 32 + ww;
                int cell_u = hh * 32 + ww + 1;
                int cell_t = (hh + 1) * 32 + ww + 1;
                int cell = isLeft ? cell_l : cell_u;
                f = g_S[(size_t)cell * 32768 + (size_t)b * 128 + dd];
                u = img[b * 1024 + cell_t];
                ++ww;
                if (ww == 31) { ww = 0; ++hh; }
            }
            __nv_bfloat16 hi = __float2bfloat16_rn(f);
            float hif = __bfloat162float(hi);
            __nv_bfloat16 lo = __float2bfloat16_rn(f - hif);
            h8[j] = __bfloat16_as_ushort(hi);
            l8[j] = __bfloat16_as_ushort(lo);
            sumF += f;
            sumUF += u * f;
            su += u;
        }
        uint4 vh, vl;
        vh.x = (uint32_t)h8[0] | ((uint32_t)h8[1] << 16);
        vh.y = (uint32_t)h8[2] | ((uint32_t)h8[3] << 16);
        vh.z = (uint32_t)h8[4] | ((uint32_t)h8[5] << 16);
        vh.w = (uint32_t)h8[6] | ((uint32_t)h8[7] << 16);
        vl.x = (uint32_t)l8[0] | ((uint32_t)l8[1] << 16);
        vl.y = (uint32_t)l8[2] | ((uint32_t)l8[3] << 16);
        vl.z = (uint32_t)l8[4] | ((uint32_t)l8[5] << 16);
        vl.w = (uint32_t)l8[6] | ((uint32_t)l8[7] << 16);
        outHi[sg] = vh;
        outLo[sg] = vl;
    }

    size_t gb = (size_t)b * GSTRIDE;
    g_G[gb + (size_t)256 * 258 + d] = sumF;
    g_G[gb + (size_t)257 * 258 + d] = sumUF;
    if (d == 0) {
        g_G[gb + (size_t)256 * 258 + 256] = 961.f;
        g_G[gb + (size_t)257 * 258 + 256] = su;
    }
}

// ---------------------------------------------------------------------------
// gram_mma (unchanged passing version)
// ---------------------------------------------------------------------------
#define SROW 72

__global__ void __launch_bounds__(256) gram_mma()
{
    extern __shared__ unsigned short sh[];
    int tile = blockIdx.x;
    int b = blockIdx.y;
    int ti = (tile > 0) ? 1 : 0;
    int tj = (tile == 2) ? 1 : 0;
    bool diag = (ti == tj);

    int tid = threadIdx.x;
    int lane = tid & 31;
    int wq = tid >> 5;
    int warp_m = wq >> 2;
    int warp_n = wq & 3;
    int l4 = lane >> 2;
    int lm2 = (lane & 3) * 2;

    unsigned short* Ahi = sh;
    unsigned short* Alo = sh + 128 * SROW;
    unsigned short* Bhi = diag ? Ahi : sh + 2 * 128 * SROW;
    unsigned short* Blo = diag ? Alo : sh + 3 * 128 * SROW;

    uint32_t uAhi = smem_u32(Ahi);
    uint32_t uAlo = smem_u32(Alo);
    uint32_t uBhi = smem_u32(Bhi);
    uint32_t uBlo = smem_u32(Blo);

    const unsigned short* srcAhi = &g_Fhi[((size_t)b * 256 + ti * 128) * 1024];
    const unsigned short* srcAlo = &g_Flo[((size_t)b * 256 + ti * 128) * 1024];
    const unsigned short* srcBhi = &g_Fhi[((size_t)b * 256 + tj * 128) * 1024];
    const unsigned short* srcBlo = &g_Flo[((size_t)b * 256 + tj * 128) * 1024];

    float d[16][4];
#pragma unroll
    for (int q = 0; q < 16; ++q)
#pragma unroll
        for (int r = 0; r < 4; ++r) d[q][r] = 0.f;

    for (int c = 0; c < 16; ++c) {
        int s0 = c * 64;
#pragma unroll
        for (int q = 0; q < 4; ++q) {
            int idx = tid + q * 256;
            int r = idx >> 3, cc = idx & 7;
            uint32_t dsto = (uint32_t)(r * SROW * 2 + cc * 16);
            size_t srco = (size_t)r * 1024 + s0 + cc * 8;
            cpasync16(uAhi + dsto, srcAhi + srco);
            cpasync16(uAlo + dsto, srcAlo + srco);
            if (!diag) {
                cpasync16(uBhi + dsto, srcBhi + srco);
                cpasync16(uBlo + dsto, srcBlo + srco);
            }
        }
        cpasync_commit();
        cpasync_wait0();
        __syncthreads();

#pragma unroll
        for (int ks = 0; ks < 4; ++ks) {
            int k0 = ks * 16;
            uint32_t aH[4][4], aL[4][4], bH[4][2], bL[4][2];
#pragma unroll
            for (int mt = 0; mt < 4; ++mt) {
                int r0 = warp_m * 64 + mt * 16 + l4;
                const unsigned short* p0 = &Ahi[r0 * SROW + k0 + lm2];
                const unsigned short* p1 = &Ahi[(r0 + 8) * SROW + k0 + lm2];
                aH[mt][0] = *(const uint32_t*)p0;
                aH[mt][1] = *(const uint32_t*)p1;
                aH[mt][2] = *(const uint32_t*)(p0 + 8);
                aH[mt][3] = *(const uint32_t*)(p1 + 8);
                const unsigned short* q0 = &Alo[r0 * SROW + k0 + lm2];
                const unsigned short* q1 = &Alo[(r0 + 8) * SROW + k0 + lm2];
                aL[mt][0] = *(const uint32_t*)q0;
                aL[mt][1] = *(const uint32_t*)q1;
                aL[mt][2] = *(const uint32_t*)(q0 + 8);
                aL[mt][3] = *(const uint32_t*)(q1 + 8);
            }
#pragma unroll
            for (int nt = 0; nt < 4; ++nt) {
                int n0 = warp_n * 32 + nt * 8 + l4;
                const unsigned short* p = &Bhi[n0 * SROW + k0 + lm2];
                bH[nt][0] = *(const uint32_t*)p;
                bH[nt][1] = *(const uint32_t*)(p + 8);
                const unsigned short* q = &Blo[n0 * SROW + k0 + lm2];
                bL[nt][0] = *(const uint32_t*)q;
                bL[nt][1] = *(const uint32_t*)(q + 8);
            }
#pragma unroll
            for (int mt = 0; mt < 4; ++mt)
#pragma unroll
                for (int nt = 0; nt < 4; ++nt) {
                    mma16816(d[mt * 4 + nt], aH[mt], bH[nt]);
                    mma16816(d[mt * 4 + nt], aL[mt], bH[nt]);
                    mma16816(d[mt * 4 + nt], aH[mt], bL[nt]);
                }
        }
        __syncthreads();
    }

    size_t gb = (size_t)b * GSTRIDE;
#pragma unroll
    for (int mt = 0; mt < 4; ++mt) {
#pragma unroll
        for (int nt = 0; nt < 4; ++nt) {
            int i0 = ti * 128 + warp_m * 64 + mt * 16 + l4;
            int j0 = tj * 128 + warp_n * 32 + nt * 8 + lm2;
            float* dst0 = &g_G[gb + (size_t)i0 * 258 + j0];
            float* dst1 = &g_G[gb + (size_t)(i0 + 8) * 258 + j0];
            *(float2*)dst0 = make_float2(d[mt * 4 + nt][0], d[mt * 4 + nt][1]);
            *(float2*)dst1 = make_float2(d[mt * 4 + nt][2], d[mt * 4 + nt][3]);
        }
    }
}

// ---------------------------------------------------------------------------
// Phase C: out-of-smem blocked Cholesky (unchanged from R7 passing version)
// ---------------------------------------------------------------------------
#define TRI(i) ((i) * ((i) + 1) / 2)
#define PTS 264
#define BRS 260

__global__ void __launch_bounds__(256, 2) solve_kernel(float* __restrict__ out)
{
    extern __shared__ float sm[];
    float* pan = sm;
    float* Pt  = sm + 8484;
    float* y   = sm + 16932;
    int b = blockIdx.x;
    int tid = threadIdx.x;
    float* A = &g_G[(size_t)b * GSTRIDE];

    for (int j = tid; j < 257; j += 256) y[j] = A[(size_t)257 * 258 + j];

    for (int kb = 0; kb < 256; kb += 32) {
        int Rf = 257 - kb;
        for (int idx = tid; idx < Rf * 32; idx += 256) {
            int r = idx >> 5, c = idx & 31;
            float v = A[(size_t)(kb + r) * 258 + kb + c];
            if (r == c) v += 25.f;
            pan[(kb + r) * 33 + c] = v;
        }
        __syncthreads();
        if (tid < 32) {
            for (int c = 0; c < 32; ++c) {
                float dsq = pan[(kb + c) * 33 + c];
                __syncwarp();
                float dv = sqrtf(dsq);
                if (tid == c) pan[(kb + c) * 33 + c] = dv;
                float lr = 0.f;
                if (tid > c) {
                    lr = pan[(kb + tid) * 33 + c] / dv;
                    pan[(kb + tid) * 33 + c] = lr;
                }
                __syncwarp();
                if (tid > c)
                    for (int c2 = c + 1; c2 <= tid; ++c2)
                        pan[(kb + tid) * 33 + c2] -= lr * pan[(kb + c2) * 33 + c];
                __syncwarp();
            }
        }
        __syncthreads();
        int base = kb + 32;
        int R = 257 - base;
        if (tid < R) {
            int i = base + tid;
            float row[32];
#pragma unroll
            for (int m = 0; m < 32; ++m) row[m] = pan[i * 33 + m];
#pragma unroll
            for (int c = 0; c < 32; ++c) {
                float v = row[c];
#pragma unroll
                for (int m = 0; m < c; ++m) v -= row[m] * pan[(kb + c) * 33 + m];
                row[c] = v / pan[(kb + c) * 33 + c];
            }
#pragma unroll
            for (int m = 0; m < 32; ++m) {
                pan[i * 33 + m] = row[m];
                Pt[m * PTS + tid] = row[m];
            }
        }
        __syncthreads();
        for (int idx = tid; idx < Rf * 32; idx += 256) {
            int r = idx >> 5, c = idx & 31;
            A[(size_t)(kb + r) * 258 + kb + c] = pan[(kb + r) * 33 + c];
        }
        if (R > 0) {
            int Gg = (R + 3) >> 2;
            int nt = Gg * (Gg + 1) / 2;
            for (int tIdx = tid; tIdx < nt; tIdx += 256) {
                int gi = (int)((sqrtf(8.f * tIdx + 1.f) - 1.f) * 0.5f);
                while (TRI(gi + 1) <= tIdx) ++gi;
                while (TRI(gi) > tIdx) --gi;
                int gj = tIdx - TRI(gi);
                int i0 = base + gi * 4, j0 = base + gj * 4;
                unsigned long long acc[4][2];
#pragma unroll
                for (int q = 0; q < 4; ++q) { acc[q][0] = 0ull; acc[q][1] = 0ull; }
#pragma unroll 8
                for (int m = 0; m < 32; ++m) {
                    float4 av = *(const float4*)&Pt[m * PTS + gi * 4];
                    ulonglong2 bv = *(const ulonglong2*)&Pt[m * PTS + gj * 4];
                    unsigned long long s;
                    s = splat2(av.x); fma2(acc[0][0], s, bv.x); fma2(acc[0][1], s, bv.y);
                    s = splat2(av.y); fma2(acc[1][0], s, bv.x); fma2(acc[1][1], s, bv.y);
                    s = splat2(av.z); fma2(acc[2][0], s, bv.x); fma2(acc[2][1], s, bv.y);
                    s = splat2(av.w); fma2(acc[3][0], s, bv.x); fma2(acc[3][1], s, bv.y);
                }
                if (i0 + 3 <= 256 && j0 + 3 <= 256) {
#pragma unroll
                    for (int q = 0; q < 4; ++q) {
                        float* ap = &A[(size_t)(i0 + q) * 258 + j0];
                        float2 o0 = *(float2*)ap;
                        float2 o1 = *(float2*)(ap + 2);
                        float2 v0 = unpk(acc[q][0]);
                        float2 v1 = unpk(acc[q][1]);
                        o0.x -= v0.x; o0.y -= v0.y;
                        o1.x -= v1.x; o1.y -= v1.y;
                        *(float2*)ap = o0;
                        *(float2*)(ap + 2) = o1;
                    }
                } else {
#pragma unroll
                    for (int q = 0; q < 4; ++q) {
                        int i = i0 + q;
                        if (i > 256) continue;
                        float2 v0 = unpk(acc[q][0]);
                        float2 v1 = unpk(acc[q][1]);
                        float vv[4] = {v0.x, v0.y, v1.x, v1.y};
#pragma unroll
                        for (int p = 0; p < 4; ++p) {
                            int j = j0 + p;
                            if (j > 256) continue;
                            A[(size_t)i * 258 + j] -= vv[p];
                        }
                    }
                }
            }
        }
        __syncthreads();
    }
    if (tid == 0)
        A[(size_t)256 * 258 + 256] = sqrtf(A[(size_t)256 * 258 + 256] + 25.f);
    __syncthreads();

    for (int kb = 0; kb < 256; kb += 32) {
        int Rf = 257 - kb;
        for (int idx = tid; idx < Rf * 32; idx += 256) {
            int r = idx >> 5, c = idx & 31;
            pan[(kb + r) * 33 + c] = A[(size_t)(kb + r) * 258 + kb + c];
        }
        __syncthreads();
        if (tid < 32) {
            float acc = y[kb + tid];
#pragma unroll
            for (int m = 0; m < 32; ++m) {
                float dm = pan[(kb + m) * 33 + m];
                if (tid == m) acc /= dm;
                float ym = __shfl_sync(0xffffffffu, acc, m);
                if (tid > m) acc -= pan[(kb + tid) * 33 + m] * ym;
            }
            y[kb + tid] = acc;
        }
        __syncthreads();
        int R = 225 - kb;
        if (tid < R) {
            int i = kb + 32 + tid;
            float acc = y[i];
#pragma unroll
            for (int c = 0; c < 32; ++c) acc -= pan[i * 33 + c] * y[kb + c];
            y[i] = acc;
        }
        __syncthreads();
    }
    if (tid == 0) y[256] /= A[(size_t)256 * 258 + 256];
    __syncthreads();

    if (tid == 0) y[256] /= A[(size_t)256 * 258 + 256];
    __syncthreads();
    {
        float x256 = y[256];
        if (tid < 256) y[tid] -= A[(size_t)256 * 258 + tid] * x256;
        __syncthreads();
    }
    for (int kb = 224; kb >= 0; kb -= 32) {
        for (int idx = tid; idx < 32 * 256; idx += 256) {
            int c = idx >> 8, j = idx & 255;
            pan[c * BRS + j] = A[(size_t)(kb + c) * 258 + j];
        }
        __syncthreads();
        if (tid < 32) {
            float acc = y[kb + tid];
#pragma unroll
            for (int m = 31; m >= 0; --m) {
                float dm = pan[m * BRS + kb + m];
                if (tid == m) acc /= dm;
                float ym = __shfl_sync(0xffffffffu, acc, m);
                if (tid < m) acc -= pan[m * BRS + kb + tid] * ym;
            }
            y[kb + tid] = acc;
        }
        __syncthreads();
        if (tid < kb) {
            float acc = y[tid];
#pragma unroll
            for (int c = 0; c < 32; ++c) acc -= pan[c * BRS + tid] * y[kb + c];
            y[tid] = acc;
        }
        __syncthreads();
    }
    for (int j = tid; j < 257; j += 256) out[b * 257 + j] = y[j];
}

// ---------------------------------------------------------------------------
extern "C" void kernel_launch(void* const* d_in, const int* in_sizes, int n_in,
                              void* d_out, int out_size)
{
    (void)in_sizes; (void)n_in; (void)out_size;
    const float* img = (const float*)d_in[0];
    const float* win = (const float*)d_in[1];
    const float* W1  = (const float*)d_in[2];
    const float* W2  = (const float*)d_in[3];
    float* out = (float*)d_out;

    int solve_smem = 17192 * (int)sizeof(float);
    cudaFuncSetAttribute(solve_kernel, cudaFuncAttributeMaxDynamicSharedMemorySize,
                         solve_smem);
    int gram_smem = 4 * 128 * SROW * 2;
    cudaFuncSetAttribute(gram_mma, cudaFuncAttributeMaxDynamicSharedMemorySize, gram_smem);

    esn_persist<<<128, 256>>>(img, win, W1, W2);
    feat_kernel<<<256, 256>>>(img);
    gram_mma<<<dim3(3, 256), 256, gram_smem>>>();
    solve_kernel<<<256, 256, solve_smem>>>(out);
}

// round 9
// speedup vs baseline: 1.0506x; 1.0506x over previous
#include <cuda_runtime.h>
#include <cuda_bf16.h>
#include <cstdint>

// ---------------------------------------------------------------------------
// ESN_2D: B=256, H=W=32, n=128, alpha^2=25, START_T=1
//  Phase A: persistent wavefront (R7 version)
//  Phase B: feat (bf16 hi/lo features) + PIPELINED mma.sync bf16-split Gram
//  Phase C: out-of-smem blocked Cholesky + blocked substitutions (R7 version)
// ---------------------------------------------------------------------------

#define GSTRIDE 66564  // 258*258

__device__ float g_S[(size_t)1024 * 256 * 128];
__device__ float g_G[(size_t)256 * GSTRIDE];
__device__ unsigned short g_Fhi[(size_t)256 * 256 * 1024];
__device__ unsigned short g_Flo[(size_t)256 * 256 * 1024];

// ---- packed f32x2 helpers ----
__device__ __forceinline__ unsigned long long splat2(float x) {
    unsigned long long r;
    asm("mov.b64 %0, {%1, %1};" : "=l"(r) : "f"(x));
    return r;
}
__device__ __forceinline__ void fma2(unsigned long long &c, unsigned long long a,
                                     unsigned long long b) {
    asm("fma.rn.f32x2 %0, %1, %2, %0;" : "+l"(c) : "l"(a), "l"(b));
}
__device__ __forceinline__ float2 unpk(unsigned long long v) {
    float2 f;
    asm("mov.b64 {%0, %1}, %2;" : "=f"(f.x), "=f"(f.y) : "l"(v));
    return f;
}

// ---- cp.async helpers ----
__device__ __forceinline__ uint32_t smem_u32(const void* p) {
    uint32_t a;
    asm("{ .reg .u64 t; cvta.to.shared.u64 t, %1; cvt.u32.u64 %0, t; }" : "=r"(a) : "l"(p));
    return a;
}
__device__ __forceinline__ void cpasync16(uint32_t dst, const void* src) {
    asm volatile("cp.async.cg.shared.global [%0], [%1], 16;" :: "r"(dst), "l"(src) : "memory");
}
__device__ __forceinline__ void cpasync_commit() {
    asm volatile("cp.async.commit_group;" ::: "memory");
}
__device__ __forceinline__ void cpasync_wait1() {
    asm volatile("cp.async.wait_group 1;" ::: "memory");
}
__device__ __forceinline__ void cpasync_wait0() {
    asm volatile("cp.async.wait_group 0;" ::: "memory");
}

// ---- bf16 mma.sync ----
__device__ __forceinline__ void mma16816(float* d, const uint32_t* a, const uint32_t* b) {
    asm volatile(
        "mma.sync.aligned.m16n8k16.row.col.f32.bf16.bf16.f32 "
        "{%0,%1,%2,%3}, {%4,%5,%6,%7}, {%8,%9}, {%0,%1,%2,%3};"
        : "+f"(d[0]), "+f"(d[1]), "+f"(d[2]), "+f"(d[3])
        : "r"(a[0]), "r"(a[1]), "r"(a[2]), "r"(a[3]), "r"(b[0]), "r"(b[1]));
}

// ---------------------------------------------------------------------------
// Phase A: persistent recurrence (R7 version). 128 CTAs, 256 threads.
// ---------------------------------------------------------------------------
__global__ void __launch_bounds__(256) esn_persist(const float* __restrict__ img,
                                                   const float* __restrict__ win,
                                                   const float* __restrict__ W1,
                                                   const float* __restrict__ W2)
{
    int b0 = blockIdx.x * 2;
    int t = threadIdx.x;
    int ip = t & 63;
    int jg = t >> 6;

    unsigned long long w1r[32], w2r[32];
#pragma unroll
    for (int m = 0; m < 32; ++m) {
        int j = jg * 32 + m;
        w1r[m] = *(const unsigned long long*)&W1[j * 128 + ip * 2];
        w2r[m] = *(const unsigned long long*)&W2[j * 128 + ip * 2];
    }

    __shared__ float rowbuf[2][32][128];
    __shared__ float lbuf[2][128];
    __shared__ float red[4][2][128];

    for (int idx = t; idx < 2 * 32 * 128; idx += 256)
        ((float*)rowbuf)[idx] = 0.f;

    int rg = t >> 7;
    int ri = t & 127;
    float winv = win[ri];

    for (int h = 0; h < 32; ++h) {
        lbuf[rg][ri] = 0.f;
        __syncthreads();
        for (int w = 0; w < 32; ++w) {
            int cell = h * 32 + w;
#pragma unroll
            for (int g = 0; g < 2; ++g) {
                unsigned long long accA = 0ull, accB = 0ull;
                const float* lb = &lbuf[g][jg * 32];
                const float* ub = &rowbuf[g][w][jg * 32];
#pragma unroll
                for (int m4 = 0; m4 < 8; ++m4) {
                    float4 lv = *(const float4*)&lb[m4 * 4];
                    float4 uv = *(const float4*)&ub[m4 * 4];
                    fma2(accA, splat2(lv.x), w1r[m4 * 4 + 0]);
                    fma2(accB, splat2(uv.x), w2r[m4 * 4 + 0]);
                    fma2(accA, splat2(lv.y), w1r[m4 * 4 + 1]);
                    fma2(accB, splat2(uv.y), w2r[m4 * 4 + 1]);
                    fma2(accA, splat2(lv.z), w1r[m4 * 4 + 2]);
                    fma2(accB, splat2(uv.z), w2r[m4 * 4 + 2]);
                    fma2(accA, splat2(lv.w), w1r[m4 * 4 + 3]);
                    fma2(accB, splat2(uv.w), w2r[m4 * 4 + 3]);
                }
                float2 a = unpk(accA), bb = unpk(accB);
                *(float2*)&red[jg][g][ip * 2] = make_float2(a.x + bb.x, a.y + bb.y);
            }
            __syncthreads();
            {
                float s = (red[0][rg][ri] + red[1][rg][ri]) +
                          (red[2][rg][ri] + red[3][rg][ri]);
                float x = img[(b0 + rg) * 1024 + cell];
                float v = tanhf(fmaf(x, winv, s));
                lbuf[rg][ri] = v;
                rowbuf[rg][w][ri] = v;
                g_S[(size_t)cell * 32768 + (size_t)(b0 + rg) * 128 + ri] = v;
            }
            __syncthreads();
        }
    }
}

// ---------------------------------------------------------------------------
// feat kernel (unchanged)
// ---------------------------------------------------------------------------
__global__ void __launch_bounds__(256) feat_kernel(const float* __restrict__ img)
{
    int b = blockIdx.x;
    int d = threadIdx.x;
    bool isLeft = d < 128;
    int dd = d & 127;

    float sumF = 0.f, sumUF = 0.f, su = 0.f;
    int hh = 0, ww = 0;

    uint4* outHi = (uint4*)&g_Fhi[((size_t)b * 256 + d) * 1024];
    uint4* outLo = (uint4*)&g_Flo[((size_t)b * 256 + d) * 1024];

    for (int sg = 0; sg < 128; ++sg) {
        unsigned short h8[8], l8[8];
#pragma unroll
        for (int j = 0; j < 8; ++j) {
            int s = sg * 8 + j;
            float f = 0.f, u = 0.f;
            if (s < 961) {
                int cell_l = (hh + 1) * 32 + ww;
                int cell_u = hh * 32 + ww + 1;
                int cell_t = (hh + 1) * 32 + ww + 1;
                int cell = isLeft ? cell_l : cell_u;
                f = g_S[(size_t)cell * 32768 + (size_t)b * 128 + dd];
                u = img[b * 1024 + cell_t];
                ++ww;
                if (ww == 31) { ww = 0; ++hh; }
            }
            __nv_bfloat16 hi = __float2bfloat16_rn(f);
            float hif = __bfloat162float(hi);
            __nv_bfloat16 lo = __float2bfloat16_rn(f - hif);
            h8[j] = __bfloat16_as_ushort(hi);
            l8[j] = __bfloat16_as_ushort(lo);
            sumF += f;
            sumUF += u * f;
            su += u;
        }
        uint4 vh, vl;
        vh.x = (uint32_t)h8[0] | ((uint32_t)h8[1] << 16);
        vh.y = (uint32_t)h8[2] | ((uint32_t)h8[3] << 16);
        vh.z = (uint32_t)h8[4] | ((uint32_t)h8[5] << 16);
        vh.w = (uint32_t)h8[6] | ((uint32_t)h8[7] << 16);
        vl.x = (uint32_t)l8[0] | ((uint32_t)l8[1] << 16);
        vl.y = (uint32_t)l8[2] | ((uint32_t)l8[3] << 16);
        vl.z = (uint32_t)l8[4] | ((uint32_t)l8[5] << 16);
        vl.w = (uint32_t)l8[6] | ((uint32_t)l8[7] << 16);
        outHi[sg] = vh;
        outLo[sg] = vl;
    }

    size_t gb = (size_t)b * GSTRIDE;
    g_G[gb + (size_t)256 * 258 + d] = sumF;
    g_G[gb + (size_t)257 * 258 + d] = sumUF;
    if (d == 0) {
        g_G[gb + (size_t)256 * 258 + 256] = 961.f;
        g_G[gb + (size_t)257 * 258 + 256] = su;
    }
}

// ---------------------------------------------------------------------------
// gram_mma: PIPELINED. 32 chunks of 32 samples, 2 smem stages (cp.async
// group per stage, wait_group 1 overlaps load(c+1) with compute(c)).
// Row stride 40 shorts: fragment-load pattern is bank-conflict-free.
// smem = 2 stages * 4 mats * 128*40*2B = 81920 B -> 2 CTAs/SM.
// ---------------------------------------------------------------------------
#define SROW2 40
#define GMAT (128 * SROW2)   // shorts per matrix per stage

__global__ void __launch_bounds__(256) gram_mma()
{
    extern __shared__ unsigned short sh[];
    int tile = blockIdx.x;
    int b = blockIdx.y;
    int ti = (tile > 0) ? 1 : 0;
    int tj = (tile == 2) ? 1 : 0;
    bool diag = (ti == tj);

    int tid = threadIdx.x;
    int lane = tid & 31;
    int wq = tid >> 5;
    int warp_m = wq >> 2;
    int warp_n = wq & 3;
    int l4 = lane >> 2;
    int lm2 = (lane & 3) * 2;

    const unsigned short* srcs[4];
    srcs[0] = &g_Fhi[((size_t)b * 256 + ti * 128) * 1024];
    srcs[1] = &g_Flo[((size_t)b * 256 + ti * 128) * 1024];
    srcs[2] = &g_Fhi[((size_t)b * 256 + tj * 128) * 1024];
    srcs[3] = &g_Flo[((size_t)b * 256 + tj * 128) * 1024];
    int nmat = diag ? 2 : 4;

    uint32_t base_u32 = smem_u32(sh);

    float d[16][4];
#pragma unroll
    for (int q = 0; q < 16; ++q)
#pragma unroll
        for (int r = 0; r < 4; ++r) d[q][r] = 0.f;

    // ---- issue loads for chunk c into stage st ----
    auto issue = [&](int c, int st) {
        int s0 = c * 32;
        uint32_t stb = base_u32 + (uint32_t)(st * 4 * GMAT * 2);
        for (int mi = 0; mi < nmat; ++mi) {
            uint32_t mb = stb + (uint32_t)(mi * GMAT * 2);
            const unsigned short* src = srcs[mi];
#pragma unroll
            for (int q = 0; q < 2; ++q) {
                int idx = tid + q * 256;
                int r = idx >> 2, cc = idx & 3;   // 4 x 16B per 32-col row
                cpasync16(mb + (uint32_t)(r * SROW2 * 2 + cc * 16),
                          src + (size_t)r * 1024 + s0 + cc * 8);
            }
        }
        cpasync_commit();
    };

    issue(0, 0);
    for (int c = 0; c < 32; ++c) {
        int st = c & 1;
        if (c + 1 < 32) { issue(c + 1, st ^ 1); cpasync_wait1(); }
        else            { cpasync_wait0(); }
        __syncthreads();

        unsigned short* stA = sh + (size_t)st * 4 * GMAT;
        unsigned short* Ahi = stA;
        unsigned short* Alo = stA + GMAT;
        unsigned short* Bhi = diag ? Ahi : stA + 2 * GMAT;
        unsigned short* Blo = diag ? Alo : stA + 3 * GMAT;

#pragma unroll
        for (int ks = 0; ks < 2; ++ks) {
            int k0 = ks * 16;
            uint32_t aH[4][4], aL[4][4], bH[4][2], bL[4][2];
#pragma unroll
            for (int mt = 0; mt < 4; ++mt) {
                int r0 = warp_m * 64 + mt * 16 + l4;
                const unsigned short* p0 = &Ahi[r0 * SROW2 + k0 + lm2];
                const unsigned short* p1 = &Ahi[(r0 + 8) * SROW2 + k0 + lm2];
                aH[mt][0] = *(const uint32_t*)p0;
                aH[mt][1] = *(const uint32_t*)p1;
                aH[mt][2] = *(const uint32_t*)(p0 + 8);
                aH[mt][3] = *(const uint32_t*)(p1 + 8);
                const unsigned short* q0 = &Alo[r0 * SROW2 + k0 + lm2];
                const unsigned short* q1 = &Alo[(r0 + 8) * SROW2 + k0 + lm2];
                aL[mt][0] = *(const uint32_t*)q0;
                aL[mt][1] = *(const uint32_t*)q1;
                aL[mt][2] = *(const uint32_t*)(q0 + 8);
                aL[mt][3] = *(const uint32_t*)(q1 + 8);
            }
#pragma unroll
            for (int nt = 0; nt < 4; ++nt) {
                int n0 = warp_n * 32 + nt * 8 + l4;
                const unsigned short* p = &Bhi[n0 * SROW2 + k0 + lm2];
                bH[nt][0] = *(const uint32_t*)p;
                bH[nt][1] = *(const uint32_t*)(p + 8);
                const unsigned short* q = &Blo[n0 * SROW2 + k0 + lm2];
                bL[nt][0] = *(const uint32_t*)q;
                bL[nt][1] = *(const uint32_t*)(q + 8);
            }
#pragma unroll
            for (int mt = 0; mt < 4; ++mt)
#pragma unroll
                for (int nt = 0; nt < 4; ++nt) {
                    mma16816(d[mt * 4 + nt], aH[mt], bH[nt]);
                    mma16816(d[mt * 4 + nt], aL[mt], bH[nt]);
                    mma16816(d[mt * 4 + nt], aH[mt], bL[nt]);
                }
        }
        __syncthreads();
    }

    size_t gb = (size_t)b * GSTRIDE;
#pragma unroll
    for (int mt = 0; mt < 4; ++mt) {
#pragma unroll
        for (int nt = 0; nt < 4; ++nt) {
            int i0 = ti * 128 + warp_m * 64 + mt * 16 + l4;
            int j0 = tj * 128 + warp_n * 32 + nt * 8 + lm2;
            float* dst0 = &g_G[gb + (size_t)i0 * 258 + j0];
            float* dst1 = &g_G[gb + (size_t)(i0 + 8) * 258 + j0];
            *(float2*)dst0 = make_float2(d[mt * 4 + nt][0], d[mt * 4 + nt][1]);
            *(float2*)dst1 = make_float2(d[mt * 4 + nt][2], d[mt * 4 + nt][3]);
        }
    }
}

// ---------------------------------------------------------------------------
// Phase C: out-of-smem blocked Cholesky (R7 passing version, unchanged)
// ---------------------------------------------------------------------------
#define TRI(i) ((i) * ((i) + 1) / 2)
#define PTS 264
#define BRS 260

__global__ void __launch_bounds__(256, 2) solve_kernel(float* __restrict__ out)
{
    extern __shared__ float sm[];
    float* pan = sm;
    float* Pt  = sm + 8484;
    float* y   = sm + 16932;
    int b = blockIdx.x;
    int tid = threadIdx.x;
    float* A = &g_G[(size_t)b * GSTRIDE];

    for (int j = tid; j < 257; j += 256) y[j] = A[(size_t)257 * 258 + j];

    for (int kb = 0; kb < 256; kb += 32) {
        int Rf = 257 - kb;
        for (int idx = tid; idx < Rf * 32; idx += 256) {
            int r = idx >> 5, c = idx & 31;
            float v = A[(size_t)(kb + r) * 258 + kb + c];
            if (r == c) v += 25.f;
            pan[(kb + r) * 33 + c] = v;
        }
        __syncthreads();
        if (tid < 32) {
            for (int c = 0; c < 32; ++c) {
                float dsq = pan[(kb + c) * 33 + c];
                __syncwarp();
                float dv = sqrtf(dsq);
                if (tid == c) pan[(kb + c) * 33 + c] = dv;
                float lr = 0.f;
                if (tid > c) {
                    lr = pan[(kb + tid) * 33 + c] / dv;
                    pan[(kb + tid) * 33 + c] = lr;
                }
                __syncwarp();
                if (tid > c)
                    for (int c2 = c + 1; c2 <= tid; ++c2)
                        pan[(kb + tid) * 33 + c2] -= lr * pan[(kb + c2) * 33 + c];
                __syncwarp();
            }
        }
        __syncthreads();
        int base = kb + 32;
        int R = 257 - base;
        if (tid < R) {
            int i = base + tid;
            float row[32];
#pragma unroll
            for (int m = 0; m < 32; ++m) row[m] = pan[i * 33 + m];
#pragma unroll
            for (int c = 0; c < 32; ++c) {
                float v = row[c];
#pragma unroll
                for (int m = 0; m < c; ++m) v -= row[m] * pan[(kb + c) * 33 + m];
                row[c] = v / pan[(kb + c) * 33 + c];
            }
#pragma unroll
            for (int m = 0; m < 32; ++m) {
                pan[i * 33 + m] = row[m];
                Pt[m * PTS + tid] = row[m];
            }
        }
        __syncthreads();
        for (int idx = tid; idx < Rf * 32; idx += 256) {
            int r = idx >> 5, c = idx & 31;
            A[(size_t)(kb + r) * 258 + kb + c] = pan[(kb + r) * 33 + c];
        }
        if (R > 0) {
            int Gg = (R + 3) >> 2;
            int nt = Gg * (Gg + 1) / 2;
            for (int tIdx = tid; tIdx < nt; tIdx += 256) {
                int gi = (int)((sqrtf(8.f * tIdx + 1.f) - 1.f) * 0.5f);
                while (TRI(gi + 1) <= tIdx) ++gi;
                while (TRI(gi) > tIdx) --gi;
                int gj = tIdx - TRI(gi);
                int i0 = base + gi * 4, j0 = base + gj * 4;
                unsigned long long acc[4][2];
#pragma unroll
                for (int q = 0; q < 4; ++q) { acc[q][0] = 0ull; acc[q][1] = 0ull; }
#pragma unroll 8
                for (int m = 0; m < 32; ++m) {
                    float4 av = *(const float4*)&Pt[m * PTS + gi * 4];
                    ulonglong2 bv = *(const ulonglong2*)&Pt[m * PTS + gj * 4];
                    unsigned long long s;
                    s = splat2(av.x); fma2(acc[0][0], s, bv.x); fma2(acc[0][1], s, bv.y);
                    s = splat2(av.y); fma2(acc[1][0], s, bv.x); fma2(acc[1][1], s, bv.y);
                    s = splat2(av.z); fma2(acc[2][0], s, bv.x); fma2(acc[2][1], s, bv.y);
                    s = splat2(av.w); fma2(acc[3][0], s, bv.x); fma2(acc[3][1], s, bv.y);
                }
                if (i0 + 3 <= 256 && j0 + 3 <= 256) {
#pragma unroll
                    for (int q = 0; q < 4; ++q) {
                        float* ap = &A[(size_t)(i0 + q) * 258 + j0];
                        float2 o0 = *(float2*)ap;
                        float2 o1 = *(float2*)(ap + 2);
                        float2 v0 = unpk(acc[q][0]);
                        float2 v1 = unpk(acc[q][1]);
                        o0.x -= v0.x; o0.y -= v0.y;
                        o1.x -= v1.x; o1.y -= v1.y;
                        *(float2*)ap = o0;
                        *(float2*)(ap + 2) = o1;
                    }
                } else {
#pragma unroll
                    for (int q = 0; q < 4; ++q) {
                        int i = i0 + q;
                        if (i > 256) continue;
                        float2 v0 = unpk(acc[q][0]);
                        float2 v1 = unpk(acc[q][1]);
                        float vv[4] = {v0.x, v0.y, v1.x, v1.y};
#pragma unroll
                        for (int p = 0; p < 4; ++p) {
                            int j = j0 + p;
                            if (j > 256) continue;
                            A[(size_t)i * 258 + j] -= vv[p];
                        }
                    }
                }
            }
        }
        __syncthreads();
    }
    if (tid == 0)
        A[(size_t)256 * 258 + 256] = sqrtf(A[(size_t)256 * 258 + 256] + 25.f);
    __syncthreads();

    for (int kb = 0; kb < 256; kb += 32) {
        int Rf = 257 - kb;
        for (int idx = tid; idx < Rf * 32; idx += 256) {
            int r = idx >> 5, c = idx & 31;
            pan[(kb + r) * 33 + c] = A[(size_t)(kb + r) * 258 + kb + c];
        }
        __syncthreads();
        if (tid < 32) {
            float acc = y[kb + tid];
#pragma unroll
            for (int m = 0; m < 32; ++m) {
                float dm = pan[(kb + m) * 33 + m];
                if (tid == m) acc /= dm;
                float ym = __shfl_sync(0xffffffffu, acc, m);
                if (tid > m) acc -= pan[(kb + tid) * 33 + m] * ym;
            }
            y[kb + tid] = acc;
        }
        __syncthreads();
        int R = 225 - kb;
        if (tid < R) {
            int i = kb + 32 + tid;
            float acc = y[i];
#pragma unroll
            for (int c = 0; c < 32; ++c) acc -= pan[i * 33 + c] * y[kb + c];
            y[i] = acc;
        }
        __syncthreads();
    }
    if (tid == 0) y[256] /= A[(size_t)256 * 258 + 256];
    __syncthreads();

    if (tid == 0) y[256] /= A[(size_t)256 * 258 + 256];
    __syncthreads();
    {
        float x256 = y[256];
        if (tid < 256) y[tid] -= A[(size_t)256 * 258 + tid] * x256;
        __syncthreads();
    }
    for (int kb = 224; kb >= 0; kb -= 32) {
        for (int idx = tid; idx < 32 * 256; idx += 256) {
            int c = idx >> 8, j = idx & 255;
            pan[c * BRS + j] = A[(size_t)(kb + c) * 258 + j];
        }
        __syncthreads();
        if (tid < 32) {
            float acc = y[kb + tid];
#pragma unroll
            for (int m = 31; m >= 0; --m) {
                float dm = pan[m * BRS + kb + m];
                if (tid == m) acc /= dm;
                float ym = __shfl_sync(0xffffffffu, acc, m);
                if (tid < m) acc -= pan[m * BRS + kb + tid] * ym;
            }
            y[kb + tid] = acc;
        }
        __syncthreads();
        if (tid < kb) {
            float acc = y[tid];
#pragma unroll
            for (int c = 0; c < 32; ++c) acc -= pan[c * BRS + tid] * y[kb + c];
            y[tid] = acc;
        }
        __syncthreads();
    }
    for (int j = tid; j < 257; j += 256) out[b * 257 + j] = y[j];
}

// ---------------------------------------------------------------------------
extern "C" void kernel_launch(void* const* d_in, const int* in_sizes, int n_in,
                              void* d_out, int out_size)
{
    (void)in_sizes; (void)n_in; (void)out_size;
    const float* img = (const float*)d_in[0];
    const float* win = (const float*)d_in[1];
    const float* W1  = (const float*)d_in[2];
    const float* W2  = (const float*)d_in[3];
    float* out = (float*)d_out;

    int solve_smem = 17192 * (int)sizeof(float);
    cudaFuncSetAttribute(solve_kernel, cudaFuncAttributeMaxDynamicSharedMemorySize,
                         solve_smem);
    int gram_smem = 2 * 4 * GMAT * 2;  // 81920 B
    cudaFuncSetAttribute(gram_mma, cudaFuncAttributeMaxDynamicSharedMemorySize, gram_smem);

    esn_persist<<<128, 256>>>(img, win, W1, W2);
    feat_kernel<<<256, 256>>>(img);
    gram_mma<<<dim3(3, 256), 256, gram_smem>>>();
    solve_kernel<<<256, 256, solve_smem>>>(out);
}

// round 10
// speedup vs baseline: 1.1235x; 1.0694x over previous
#include <cuda_runtime.h>
#include <cuda_bf16.h>
#include <cstdint>

// ---------------------------------------------------------------------------
// ESN_2D: B=256, H=W=32, n=128, alpha^2=25, START_T=1
//  Phase A: persistent wavefront (R7 version)
//  Phase B: feat_init + 4-slab feat (bf16 hi/lo features, atomic row sums)
//           + pipelined mma.sync bf16-split Gram (R9 version)
//  Phase C: out-of-smem blocked Cholesky + blocked substitutions (R7 version)
// ---------------------------------------------------------------------------

#define GSTRIDE 66564  // 258*258

__device__ float g_S[(size_t)1024 * 256 * 128];
__device__ float g_G[(size_t)256 * GSTRIDE];
__device__ unsigned short g_Fhi[(size_t)256 * 256 * 1024];
__device__ unsigned short g_Flo[(size_t)256 * 256 * 1024];

// ---- packed f32x2 helpers ----
__device__ __forceinline__ unsigned long long splat2(float x) {
    unsigned long long r;
    asm("mov.b64 %0, {%1, %1};" : "=l"(r) : "f"(x));
    return r;
}
__device__ __forceinline__ void fma2(unsigned long long &c, unsigned long long a,
                                     unsigned long long b) {
    asm("fma.rn.f32x2 %0, %1, %2, %0;" : "+l"(c) : "l"(a), "l"(b));
}
__device__ __forceinline__ float2 unpk(unsigned long long v) {
    float2 f;
    asm("mov.b64 {%0, %1}, %2;" : "=f"(f.x), "=f"(f.y) : "l"(v));
    return f;
}

// ---- cp.async helpers ----
__device__ __forceinline__ uint32_t smem_u32(const void* p) {
    uint32_t a;
    asm("{ .reg .u64 t; cvta.to.shared.u64 t, %1; cvt.u32.u64 %0, t; }" : "=r"(a) : "l"(p));
    return a;
}
__device__ __forceinline__ void cpasync16(uint32_t dst, const void* src) {
    asm volatile("cp.async.cg.shared.global [%0], [%1], 16;" :: "r"(dst), "l"(src) : "memory");
}
__device__ __forceinline__ void cpasync_commit() {
    asm volatile("cp.async.commit_group;" ::: "memory");
}
__device__ __forceinline__ void cpasync_wait1() {
    asm volatile("cp.async.wait_group 1;" ::: "memory");
}
__device__ __forceinline__ void cpasync_wait0() {
    asm volatile("cp.async.wait_group 0;" ::: "memory");
}

// ---- bf16 mma.sync ----
__device__ __forceinline__ void mma16816(float* d, const uint32_t* a, const uint32_t* b) {
    asm volatile(
        "mma.sync.aligned.m16n8k16.row.col.f32.bf16.bf16.f32 "
        "{%0,%1,%2,%3}, {%4,%5,%6,%7}, {%8,%9}, {%0,%1,%2,%3};"
        : "+f"(d[0]), "+f"(d[1]), "+f"(d[2]), "+f"(d[3])
        : "r"(a[0]), "r"(a[1]), "r"(a[2]), "r"(a[3]), "r"(b[0]), "r"(b[1]));
}

// ---------------------------------------------------------------------------
// Phase A: persistent recurrence (R7 version). 128 CTAs, 256 threads.
// ---------------------------------------------------------------------------
__global__ void __launch_bounds__(256) esn_persist(const float* __restrict__ img,
                                                   const float* __restrict__ win,
                                                   const float* __restrict__ W1,
                                                   const float* __restrict__ W2)
{
    int b0 = blockIdx.x * 2;
    int t = threadIdx.x;
    int ip = t & 63;
    int jg = t >> 6;

    unsigned long long w1r[32], w2r[32];
#pragma unroll
    for (int m = 0; m < 32; ++m) {
        int j = jg * 32 + m;
        w1r[m] = *(const unsigned long long*)&W1[j * 128 + ip * 2];
        w2r[m] = *(const unsigned long long*)&W2[j * 128 + ip * 2];
    }

    __shared__ float rowbuf[2][32][128];
    __shared__ float lbuf[2][128];
    __shared__ float red[4][2][128];

    for (int idx = t; idx < 2 * 32 * 128; idx += 256)
        ((float*)rowbuf)[idx] = 0.f;

    int rg = t >> 7;
    int ri = t & 127;
    float winv = win[ri];

    for (int h = 0; h < 32; ++h) {
        lbuf[rg][ri] = 0.f;
        __syncthreads();
        for (int w = 0; w < 32; ++w) {
            int cell = h * 32 + w;
#pragma unroll
            for (int g = 0; g < 2; ++g) {
                unsigned long long accA = 0ull, accB = 0ull;
                const float* lb = &lbuf[g][jg * 32];
                const float* ub = &rowbuf[g][w][jg * 32];
#pragma unroll
                for (int m4 = 0; m4 < 8; ++m4) {
                    float4 lv = *(const float4*)&lb[m4 * 4];
                    float4 uv = *(const float4*)&ub[m4 * 4];
                    fma2(accA, splat2(lv.x), w1r[m4 * 4 + 0]);
                    fma2(accB, splat2(uv.x), w2r[m4 * 4 + 0]);
                    fma2(accA, splat2(lv.y), w1r[m4 * 4 + 1]);
                    fma2(accB, splat2(uv.y), w2r[m4 * 4 + 1]);
                    fma2(accA, splat2(lv.z), w1r[m4 * 4 + 2]);
                    fma2(accB, splat2(uv.z), w2r[m4 * 4 + 2]);
                    fma2(accA, splat2(lv.w), w1r[m4 * 4 + 3]);
                    fma2(accB, splat2(uv.w), w2r[m4 * 4 + 3]);
                }
                float2 a = unpk(accA), bb = unpk(accB);
                *(float2*)&red[jg][g][ip * 2] = make_float2(a.x + bb.x, a.y + bb.y);
            }
            __syncthreads();
            {
                float s = (red[0][rg][ri] + red[1][rg][ri]) +
                          (red[2][rg][ri] + red[3][rg][ri]);
                float x = img[(b0 + rg) * 1024 + cell];
                float v = tanhf(fmaf(x, winv, s));
                lbuf[rg][ri] = v;
                rowbuf[rg][w][ri] = v;
                g_S[(size_t)cell * 32768 + (size_t)(b0 + rg) * 128 + ri] = v;
            }
            __syncthreads();
        }
    }
}

// ---------------------------------------------------------------------------
// feat_init: zero Gram rows 256/257, set exact count. grid=256, block=256.
// ---------------------------------------------------------------------------
__global__ void __launch_bounds__(256) feat_init()
{
    size_t gb = (size_t)blockIdx.x * GSTRIDE;
    for (int j = threadIdx.x; j < 258; j += 256) {
        g_G[gb + (size_t)256 * 258 + j] = 0.f;
        g_G[gb + (size_t)257 * 258 + j] = 0.f;
    }
    if (threadIdx.x == 0) g_G[gb + (size_t)256 * 258 + 256] = 961.f;
}

// ---------------------------------------------------------------------------
// feat: 4 sample-slabs per batch. grid=(4, 256), block=256 (d).
// Each thread converts 256 samples; row sums accumulated via atomicAdd.
// ---------------------------------------------------------------------------
__global__ void __launch_bounds__(256) feat_kernel(const float* __restrict__ img)
{
    int slab = blockIdx.x;
    int b = blockIdx.y;
    int d = threadIdx.x;
    bool isLeft = d < 128;
    int dd = d & 127;

    int s0 = slab * 256;
    int hh = s0 / 31;
    int ww = s0 - hh * 31;

    float sumF = 0.f, sumUF = 0.f, su = 0.f;

    uint4* outHi = (uint4*)&g_Fhi[((size_t)b * 256 + d) * 1024] + s0 / 8;
    uint4* outLo = (uint4*)&g_Flo[((size_t)b * 256 + d) * 1024] + s0 / 8;

    for (int sg = 0; sg < 32; ++sg) {
        unsigned short h8[8], l8[8];
#pragma unroll
        for (int j = 0; j < 8; ++j) {
            int s = s0 + sg * 8 + j;
            float f = 0.f, u = 0.f;
            if (s < 961) {
                int cell_l = (hh + 1) * 32 + ww;
                int cell_u = hh * 32 + ww + 1;
                int cell_t = (hh + 1) * 32 + ww + 1;
                int cell = isLeft ? cell_l : cell_u;
                f = g_S[(size_t)cell * 32768 + (size_t)b * 128 + dd];
                u = img[b * 1024 + cell_t];
                ++ww;
                if (ww == 31) { ww = 0; ++hh; }
            }
            __nv_bfloat16 hi = __float2bfloat16_rn(f);
            float hif = __bfloat162float(hi);
            __nv_bfloat16 lo = __float2bfloat16_rn(f - hif);
            h8[j] = __bfloat16_as_ushort(hi);
            l8[j] = __bfloat16_as_ushort(lo);
            sumF += f;
            sumUF += u * f;
            su += u;
        }
        uint4 vh, vl;
        vh.x = (uint32_t)h8[0] | ((uint32_t)h8[1] << 16);
        vh.y = (uint32_t)h8[2] | ((uint32_t)h8[3] << 16);
        vh.z = (uint32_t)h8[4] | ((uint32_t)h8[5] << 16);
        vh.w = (uint32_t)h8[6] | ((uint32_t)h8[7] << 16);
        vl.x = (uint32_t)l8[0] | ((uint32_t)l8[1] << 16);
        vl.y = (uint32_t)l8[2] | ((uint32_t)l8[3] << 16);
        vl.z = (uint32_t)l8[4] | ((uint32_t)l8[5] << 16);
        vl.w = (uint32_t)l8[6] | ((uint32_t)l8[7] << 16);
        outHi[sg] = vh;
        outLo[sg] = vl;
    }

    size_t gb = (size_t)b * GSTRIDE;
    atomicAdd(&g_G[gb + (size_t)256 * 258 + d], sumF);
    atomicAdd(&g_G[gb + (size_t)257 * 258 + d], sumUF);
    if (d == 0) atomicAdd(&g_G[gb + (size_t)257 * 258 + 256], su);
}

// ---------------------------------------------------------------------------
// gram_mma: pipelined (R9 passing version, unchanged)
// ---------------------------------------------------------------------------
#define SROW2 40
#define GMAT (128 * SROW2)

__global__ void __launch_bounds__(256) gram_mma()
{
    extern __shared__ unsigned short sh[];
    int tile = blockIdx.x;
    int b = blockIdx.y;
    int ti = (tile > 0) ? 1 : 0;
    int tj = (tile == 2) ? 1 : 0;
    bool diag = (ti == tj);

    int tid = threadIdx.x;
    int lane = tid & 31;
    int wq = tid >> 5;
    int warp_m = wq >> 2;
    int warp_n = wq & 3;
    int l4 = lane >> 2;
    int lm2 = (lane & 3) * 2;

    const unsigned short* srcs[4];
    srcs[0] = &g_Fhi[((size_t)b * 256 + ti * 128) * 1024];
    srcs[1] = &g_Flo[((size_t)b * 256 + ti * 128) * 1024];
    srcs[2] = &g_Fhi[((size_t)b * 256 + tj * 128) * 1024];
    srcs[3] = &g_Flo[((size_t)b * 256 + tj * 128) * 1024];
    int nmat = diag ? 2 : 4;

    uint32_t base_u32 = smem_u32(sh);

    float d[16][4];
#pragma unroll
    for (int q = 0; q < 16; ++q)
#pragma unroll
        for (int r = 0; r < 4; ++r) d[q][r] = 0.f;

    auto issue = [&](int c, int st) {
        int s0 = c * 32;
        uint32_t stb = base_u32 + (uint32_t)(st * 4 * GMAT * 2);
        for (int mi = 0; mi < nmat; ++mi) {
            uint32_t mb = stb + (uint32_t)(mi * GMAT * 2);
            const unsigned short* src = srcs[mi];
#pragma unroll
            for (int q = 0; q < 2; ++q) {
                int idx = tid + q * 256;
                int r = idx >> 2, cc = idx & 3;
                cpasync16(mb + (uint32_t)(r * SROW2 * 2 + cc * 16),
                          src + (size_t)r * 1024 + s0 + cc * 8);
            }
        }
        cpasync_commit();
    };

    issue(0, 0);
    for (int c = 0; c < 32; ++c) {
        int st = c & 1;
        if (c + 1 < 32) { issue(c + 1, st ^ 1); cpasync_wait1(); }
        else            { cpasync_wait0(); }
        __syncthreads();

        unsigned short* stA = sh + (size_t)st * 4 * GMAT;
        unsigned short* Ahi = stA;
        unsigned short* Alo = stA + GMAT;
        unsigned short* Bhi = diag ? Ahi : stA + 2 * GMAT;
        unsigned short* Blo = diag ? Alo : stA + 3 * GMAT;

#pragma unroll
        for (int ks = 0; ks < 2; ++ks) {
            int k0 = ks * 16;
            uint32_t aH[4][4], aL[4][4], bH[4][2], bL[4][2];
#pragma unroll
            for (int mt = 0; mt < 4; ++mt) {
                int r0 = warp_m * 64 + mt * 16 + l4;
                const unsigned short* p0 = &Ahi[r0 * SROW2 + k0 + lm2];
                const unsigned short* p1 = &Ahi[(r0 + 8) * SROW2 + k0 + lm2];
                aH[mt][0] = *(const uint32_t*)p0;
                aH[mt][1] = *(const uint32_t*)p1;
                aH[mt][2] = *(const uint32_t*)(p0 + 8);
                aH[mt][3] = *(const uint32_t*)(p1 + 8);
                const unsigned short* q0 = &Alo[r0 * SROW2 + k0 + lm2];
                const unsigned short* q1 = &Alo[(r0 + 8) * SROW2 + k0 + lm2];
                aL[mt][0] = *(const uint32_t*)q0;
                aL[mt][1] = *(const uint32_t*)q1;
                aL[mt][2] = *(const uint32_t*)(q0 + 8);
                aL[mt][3] = *(const uint32_t*)(q1 + 8);
            }
#pragma unroll
            for (int nt = 0; nt < 4; ++nt) {
                int n0 = warp_n * 32 + nt * 8 + l4;
                const unsigned short* p = &Bhi[n0 * SROW2 + k0 + lm2];
                bH[nt][0] = *(const uint32_t*)p;
                bH[nt][1] = *(const uint32_t*)(p + 8);
                const unsigned short* q = &Blo[n0 * SROW2 + k0 + lm2];
                bL[nt][0] = *(const uint32_t*)q;
                bL[nt][1] = *(const uint32_t*)(q + 8);
            }
#pragma unroll
            for (int mt = 0; mt < 4; ++mt)
#pragma unroll
                for (int nt = 0; nt < 4; ++nt) {
                    mma16816(d[mt * 4 + nt], aH[mt], bH[nt]);
                    mma16816(d[mt * 4 + nt], aL[mt], bH[nt]);
                    mma16816(d[mt * 4 + nt], aH[mt], bL[nt]);
                }
        }
        __syncthreads();
    }

    size_t gb = (size_t)b * GSTRIDE;
#pragma unroll
    for (int mt = 0; mt < 4; ++mt) {
#pragma unroll
        for (int nt = 0; nt < 4; ++nt) {
            int i0 = ti * 128 + warp_m * 64 + mt * 16 + l4;
            int j0 = tj * 128 + warp_n * 32 + nt * 8 + lm2;
            float* dst0 = &g_G[gb + (size_t)i0 * 258 + j0];
            float* dst1 = &g_G[gb + (size_t)(i0 + 8) * 258 + j0];
            *(float2*)dst0 = make_float2(d[mt * 4 + nt][0], d[mt * 4 + nt][1]);
            *(float2*)dst1 = make_float2(d[mt * 4 + nt][2], d[mt * 4 + nt][3]);
        }
    }
}

// ---------------------------------------------------------------------------
// Phase C: out-of-smem blocked Cholesky (R7 passing version, unchanged)
// ---------------------------------------------------------------------------
#define TRI(i) ((i) * ((i) + 1) / 2)
#define PTS 264
#define BRS 260

__global__ void __launch_bounds__(256, 2) solve_kernel(float* __restrict__ out)
{
    extern __shared__ float sm[];
    float* pan = sm;
    float* Pt  = sm + 8484;
    float* y   = sm + 16932;
    int b = blockIdx.x;
    int tid = threadIdx.x;
    float* A = &g_G[(size_t)b * GSTRIDE];

    for (int j = tid; j < 257; j += 256) y[j] = A[(size_t)257 * 258 + j];

    for (int kb = 0; kb < 256; kb += 32) {
        int Rf = 257 - kb;
        for (int idx = tid; idx < Rf * 32; idx += 256) {
            int r = idx >> 5, c = idx & 31;
            float v = A[(size_t)(kb + r) * 258 + kb + c];
            if (r == c) v += 25.f;
            pan[(kb + r) * 33 + c] = v;
        }
        __syncthreads();
        if (tid < 32) {
            for (int c = 0; c < 32; ++c) {
                float dsq = pan[(kb + c) * 33 + c];
                __syncwarp();
                float dv = sqrtf(dsq);
                if (tid == c) pan[(kb + c) * 33 + c] = dv;
                float lr = 0.f;
                if (tid > c) {
                    lr = pan[(kb + tid) * 33 + c] / dv;
                    pan[(kb + tid) * 33 + c] = lr;
                }
                __syncwarp();
                if (tid > c)
                    for (int c2 = c + 1; c2 <= tid; ++c2)
                        pan[(kb + tid) * 33 + c2] -= lr * pan[(kb + c2) * 33 + c];
                __syncwarp();
            }
        }
        __syncthreads();
        int base = kb + 32;
        int R = 257 - base;
        if (tid < R) {
            int i = base + tid;
            float row[32];
#pragma unroll
            for (int m = 0; m < 32; ++m) row[m] = pan[i * 33 + m];
#pragma unroll
            for (int c = 0; c < 32; ++c) {
                float v = row[c];
#pragma unroll
                for (int m = 0; m < c; ++m) v -= row[m] * pan[(kb + c) * 33 + m];
                row[c] = v / pan[(kb + c) * 33 + c];
            }
#pragma unroll
            for (int m = 0; m < 32; ++m) {
                pan[i * 33 + m] = row[m];
                Pt[m * PTS + tid] = row[m];
            }
        }
        __syncthreads();
        for (int idx = tid; idx < Rf * 32; idx += 256) {
            int r = idx >> 5, c = idx & 31;
            A[(size_t)(kb + r) * 258 + kb + c] = pan[(kb + r) * 33 + c];
        }
        if (R > 0) {
            int Gg = (R + 3) >> 2;
            int nt = Gg * (Gg + 1) / 2;
            for (int tIdx = tid; tIdx < nt; tIdx += 256) {
                int gi = (int)((sqrtf(8.f * tIdx + 1.f) - 1.f) * 0.5f);
                while (TRI(gi + 1) <= tIdx) ++gi;
                while (TRI(gi) > tIdx) --gi;
                int gj = tIdx - TRI(gi);
                int i0 = base + gi * 4, j0 = base + gj * 4;
                unsigned long long acc[4][2];
#pragma unroll
                for (int q = 0; q < 4; ++q) { acc[q][0] = 0ull; acc[q][1] = 0ull; }
#pragma unroll 8
                for (int m = 0; m < 32; ++m) {
                    float4 av = *(const float4*)&Pt[m * PTS + gi * 4];
                    ulonglong2 bv = *(const ulonglong2*)&Pt[m * PTS + gj * 4];
                    unsigned long long s;
                    s = splat2(av.x); fma2(acc[0][0], s, bv.x); fma2(acc[0][1], s, bv.y);
                    s = splat2(av.y); fma2(acc[1][0], s, bv.x); fma2(acc[1][1], s, bv.y);
                    s = splat2(av.z); fma2(acc[2][0], s, bv.x); fma2(acc[2][1], s, bv.y);
                    s = splat2(av.w); fma2(acc[3][0], s, bv.x); fma2(acc[3][1], s, bv.y);
                }
                if (i0 + 3 <= 256 && j0 + 3 <= 256) {
#pragma unroll
                    for (int q = 0; q < 4; ++q) {
                        float* ap = &A[(size_t)(i0 + q) * 258 + j0];
                        float2 o0 = *(float2*)ap;
                        float2 o1 = *(float2*)(ap + 2);
                        float2 v0 = unpk(acc[q][0]);
                        float2 v1 = unpk(acc[q][1]);
                        o0.x -= v0.x; o0.y -= v0.y;
                        o1.x -= v1.x; o1.y -= v1.y;
                        *(float2*)ap = o0;
                        *(float2*)(ap + 2) = o1;
                    }
                } else {
#pragma unroll
                    for (int q = 0; q < 4; ++q) {
                        int i = i0 + q;
                        if (i > 256) continue;
                        float2 v0 = unpk(acc[q][0]);
                        float2 v1 = unpk(acc[q][1]);
                        float vv[4] = {v0.x, v0.y, v1.x, v1.y};
#pragma unroll
                        for (int p = 0; p < 4; ++p) {
                            int j = j0 + p;
                            if (j > 256) continue;
                            A[(size_t)i * 258 + j] -= vv[p];
                        }
                    }
                }
            }
        }
        __syncthreads();
    }
    if (tid == 0)
        A[(size_t)256 * 258 + 256] = sqrtf(A[(size_t)256 * 258 + 256] + 25.f);
    __syncthreads();

    for (int kb = 0; kb < 256; kb += 32) {
        int Rf = 257 - kb;
        for (int idx = tid; idx < Rf * 32; idx += 256) {
            int r = idx >> 5, c = idx & 31;
            pan[(kb + r) * 33 + c] = A[(size_t)(kb + r) * 258 + kb + c];
        }
        __syncthreads();
        if (tid < 32) {
            float acc = y[kb + tid];
#pragma unroll
            for (int m = 0; m < 32; ++m) {
                float dm = pan[(kb + m) * 33 + m];
                if (tid == m) acc /= dm;
                float ym = __shfl_sync(0xffffffffu, acc, m);
                if (tid > m) acc -= pan[(kb + tid) * 33 + m] * ym;
            }
            y[kb + tid] = acc;
        }
        __syncthreads();
        int R = 225 - kb;
        if (tid < R) {
            int i = kb + 32 + tid;
            float acc = y[i];
#pragma unroll
            for (int c = 0; c < 32; ++c) acc -= pan[i * 33 + c] * y[kb + c];
            y[i] = acc;
        }
        __syncthreads();
    }
    if (tid == 0) y[256] /= A[(size_t)256 * 258 + 256];
    __syncthreads();

    if (tid == 0) y[256] /= A[(size_t)256 * 258 + 256];
    __syncthreads();
    {
        float x256 = y[256];
        if (tid < 256) y[tid] -= A[(size_t)256 * 258 + tid] * x256;
        __syncthreads();
    }
    for (int kb = 224; kb >= 0; kb -= 32) {
        for (int idx = tid; idx < 32 * 256; idx += 256) {
            int c = idx >> 8, j = idx & 255;
            pan[c * BRS + j] = A[(size_t)(kb + c) * 258 + j];
        }
        __syncthreads();
        if (tid < 32) {
            float acc = y[kb + tid];
#pragma unroll
            for (int m = 31; m >= 0; --m) {
                float dm = pan[m * BRS + kb + m];
                if (tid == m) acc /= dm;
                float ym = __shfl_sync(0xffffffffu, acc, m);
                if (tid < m) acc -= pan[m * BRS + kb + tid] * ym;
            }
            y[kb + tid] = acc;
        }
        __syncthreads();
        if (tid < kb) {
            float acc = y[tid];
#pragma unroll
            for (int c = 0; c < 32; ++c) acc -= pan[c * BRS + tid] * y[kb + c];
            y[tid] = acc;
        }
        __syncthreads();
    }
    for (int j = tid; j < 257; j += 256) out[b * 257 + j] = y[j];
}

// ---------------------------------------------------------------------------
extern "C" void kernel_launch(void* const* d_in, const int* in_sizes, int n_in,
                              void* d_out, int out_size)
{
    (void)in_sizes; (void)n_in; (void)out_size;
    const float* img = (const float*)d_in[0];
    const float* win = (const float*)d_in[1];
    const float* W1  = (const float*)d_in[2];
    const float* W2  = (const float*)d_in[3];
    float* out = (float*)d_out;

    int solve_smem = 17192 * (int)sizeof(float);
    cudaFuncSetAttribute(solve_kernel, cudaFuncAttributeMaxDynamicSharedMemorySize,
                         solve_smem);
    int gram_smem = 2 * 4 * GMAT * 2;  // 81920 B
    cudaFuncSetAttribute(gram_mma, cudaFuncAttributeMaxDynamicSharedMemorySize, gram_smem);

    esn_persist<<<128, 256>>>(img, win, W1, W2);
    feat_init<<<256, 256>>>();
    feat_kernel<<<dim3(4, 256), 256>>>(img);
    gram_mma<<<dim3(3, 256), 256, gram_smem>>>();
    solve_kernel<<<256, 256, solve_smem>>>(out);
}

// round 11
// speedup vs baseline: 1.1256x; 1.0019x over previous
#include <cuda_runtime.h>
#include <cuda_bf16.h>
#include <cstdint>

// ---------------------------------------------------------------------------
// ESN_2D: B=256, H=W=32, n=128, alpha^2=25, START_T=1
//  Phase A: persistent wavefront (fast tanh via MUFU exp/rcp)
//  Phase B: feat_init + 4-slab feat (bf16x2-vectorized conversion)
//           + pipelined mma.sync bf16-split Gram
//  Phase C: out-of-smem blocked Cholesky + blocked substitutions
// ---------------------------------------------------------------------------

#define GSTRIDE 66564  // 258*258

__device__ float g_S[(size_t)1024 * 256 * 128];
__device__ float g_G[(size_t)256 * GSTRIDE];
__device__ unsigned short g_Fhi[(size_t)256 * 256 * 1024];
__device__ unsigned short g_Flo[(size_t)256 * 256 * 1024];

// ---- packed f32x2 helpers ----
__device__ __forceinline__ unsigned long long splat2(float x) {
    unsigned long long r;
    asm("mov.b64 %0, {%1, %1};" : "=l"(r) : "f"(x));
    return r;
}
__device__ __forceinline__ void fma2(unsigned long long &c, unsigned long long a,
                                     unsigned long long b) {
    asm("fma.rn.f32x2 %0, %1, %2, %0;" : "+l"(c) : "l"(a), "l"(b));
}
__device__ __forceinline__ float2 unpk(unsigned long long v) {
    float2 f;
    asm("mov.b64 {%0, %1}, %2;" : "=f"(f.x), "=f"(f.y) : "l"(v));
    return f;
}

// ---- cp.async helpers ----
__device__ __forceinline__ uint32_t smem_u32(const void* p) {
    uint32_t a;
    asm("{ .reg .u64 t; cvta.to.shared.u64 t, %1; cvt.u32.u64 %0, t; }" : "=r"(a) : "l"(p));
    return a;
}
__device__ __forceinline__ void cpasync16(uint32_t dst, const void* src) {
    asm volatile("cp.async.cg.shared.global [%0], [%1], 16;" :: "r"(dst), "l"(src) : "memory");
}
__device__ __forceinline__ void cpasync_commit() {
    asm volatile("cp.async.commit_group;" ::: "memory");
}
__device__ __forceinline__ void cpasync_wait1() {
    asm volatile("cp.async.wait_group 1;" ::: "memory");
}
__device__ __forceinline__ void cpasync_wait0() {
    asm volatile("cp.async.wait_group 0;" ::: "memory");
}

// ---- bf16 mma.sync ----
__device__ __forceinline__ void mma16816(float* d, const uint32_t* a, const uint32_t* b) {
    asm volatile(
        "mma.sync.aligned.m16n8k16.row.col.f32.bf16.bf16.f32 "
        "{%0,%1,%2,%3}, {%4,%5,%6,%7}, {%8,%9}, {%0,%1,%2,%3};"
        : "+f"(d[0]), "+f"(d[1]), "+f"(d[2]), "+f"(d[3])
        : "r"(a[0]), "r"(a[1]), "r"(a[2]), "r"(a[3]), "r"(b[0]), "r"(b[1]));
}

// fast tanh: 1 - 2/(e^{2x}+1), MUFU-based, rel err ~1e-6
__device__ __forceinline__ float fast_tanh(float x) {
    float e = __expf(2.f * x);
    return 1.f - __fdividef(2.f, e + 1.f);
}

// pack two f32 to bf16x2 (lo half = a, hi half = b), round-to-nearest
__device__ __forceinline__ uint32_t bf16x2_rn(float a, float b) {
    uint32_t r;
    asm("cvt.rn.bf16x2.f32 %0, %1, %2;" : "=r"(r) : "f"(b), "f"(a));
    return r;
}

// ---------------------------------------------------------------------------
// Phase A: persistent recurrence. 128 CTAs (2 batches each), 256 threads.
// ---------------------------------------------------------------------------
__global__ void __launch_bounds__(256) esn_persist(const float* __restrict__ img,
                                                   const float* __restrict__ win,
                                                   const float* __restrict__ W1,
                                                   const float* __restrict__ W2)
{
    int b0 = blockIdx.x * 2;
    int t = threadIdx.x;
    int ip = t & 63;
    int jg = t >> 6;

    unsigned long long w1r[32], w2r[32];
#pragma unroll
    for (int m = 0; m < 32; ++m) {
        int j = jg * 32 + m;
        w1r[m] = *(const unsigned long long*)&W1[j * 128 + ip * 2];
        w2r[m] = *(const unsigned long long*)&W2[j * 128 + ip * 2];
    }

    __shared__ float rowbuf[2][32][128];
    __shared__ float lbuf[2][128];
    __shared__ float red[4][2][128];

    for (int idx = t; idx < 2 * 32 * 128; idx += 256)
        ((float*)rowbuf)[idx] = 0.f;

    int rg = t >> 7;
    int ri = t & 127;
    float winv = win[ri];

    for (int h = 0; h < 32; ++h) {
        lbuf[rg][ri] = 0.f;
        __syncthreads();
        for (int w = 0; w < 32; ++w) {
            int cell = h * 32 + w;
#pragma unroll
            for (int g = 0; g < 2; ++g) {
                unsigned long long accA = 0ull, accB = 0ull;
                const float* lb = &lbuf[g][jg * 32];
                const float* ub = &rowbuf[g][w][jg * 32];
#pragma unroll
                for (int m4 = 0; m4 < 8; ++m4) {
                    float4 lv = *(const float4*)&lb[m4 * 4];
                    float4 uv = *(const float4*)&ub[m4 * 4];
                    fma2(accA, splat2(lv.x), w1r[m4 * 4 + 0]);
                    fma2(accB, splat2(uv.x), w2r[m4 * 4 + 0]);
                    fma2(accA, splat2(lv.y), w1r[m4 * 4 + 1]);
                    fma2(accB, splat2(uv.y), w2r[m4 * 4 + 1]);
                    fma2(accA, splat2(lv.z), w1r[m4 * 4 + 2]);
                    fma2(accB, splat2(uv.z), w2r[m4 * 4 + 2]);
                    fma2(accA, splat2(lv.w), w1r[m4 * 4 + 3]);
                    fma2(accB, splat2(uv.w), w2r[m4 * 4 + 3]);
                }
                float2 a = unpk(accA), bb = unpk(accB);
                *(float2*)&red[jg][g][ip * 2] = make_float2(a.x + bb.x, a.y + bb.y);
            }
            __syncthreads();
            {
                float s = (red[0][rg][ri] + red[1][rg][ri]) +
                          (red[2][rg][ri] + red[3][rg][ri]);
                float x = img[(b0 + rg) * 1024 + cell];
                float v = fast_tanh(fmaf(x, winv, s));
                lbuf[rg][ri] = v;
                rowbuf[rg][w][ri] = v;
                g_S[(size_t)cell * 32768 + (size_t)(b0 + rg) * 128 + ri] = v;
            }
            __syncthreads();
        }
    }
}

// ---------------------------------------------------------------------------
// feat_init: zero Gram rows 256/257, set exact count. grid=256, block=256.
// ---------------------------------------------------------------------------
__global__ void __launch_bounds__(256) feat_init()
{
    size_t gb = (size_t)blockIdx.x * GSTRIDE;
    for (int j = threadIdx.x; j < 258; j += 256) {
        g_G[gb + (size_t)256 * 258 + j] = 0.f;
        g_G[gb + (size_t)257 * 258 + j] = 0.f;
    }
    if (threadIdx.x == 0) g_G[gb + (size_t)256 * 258 + 256] = 961.f;
}

// ---------------------------------------------------------------------------
// feat: 4 sample-slabs per batch, bf16x2-pair vectorized conversion.
// grid=(4, 256), block=256 (d). Row sums via atomicAdd.
// ---------------------------------------------------------------------------
__global__ void __launch_bounds__(256) feat_kernel(const float* __restrict__ img)
{
    int slab = blockIdx.x;
    int b = blockIdx.y;
    int d = threadIdx.x;
    bool isLeft = d < 128;
    int dd = d & 127;

    int s0 = slab * 256;
    int hh = s0 / 31;
    int ww = s0 - hh * 31;

    float sumF = 0.f, sumUF = 0.f, su = 0.f;

    uint4* outHi = (uint4*)&g_Fhi[((size_t)b * 256 + d) * 1024] + s0 / 8;
    uint4* outLo = (uint4*)&g_Flo[((size_t)b * 256 + d) * 1024] + s0 / 8;

    for (int sg = 0; sg < 32; ++sg) {
        uint32_t hw[4], lw[4];
#pragma unroll
        for (int jp = 0; jp < 4; ++jp) {
            float f0 = 0.f, u0 = 0.f, f1 = 0.f, u1 = 0.f;
            int s = s0 + sg * 8 + jp * 2;
            if (s < 961) {
                int cell = isLeft ? ((hh + 1) * 32 + ww) : (hh * 32 + ww + 1);
                f0 = g_S[(size_t)cell * 32768 + (size_t)b * 128 + dd];
                u0 = img[b * 1024 + (hh + 1) * 32 + ww + 1];
                ++ww;
                if (ww == 31) { ww = 0; ++hh; }
            }
            if (s + 1 < 961) {
                int cell = isLeft ? ((hh + 1) * 32 + ww) : (hh * 32 + ww + 1);
                f1 = g_S[(size_t)cell * 32768 + (size_t)b * 128 + dd];
                u1 = img[b * 1024 + (hh + 1) * 32 + ww + 1];
                ++ww;
                if (ww == 31) { ww = 0; ++hh; }
            }
            uint32_t hp = bf16x2_rn(f0, f1);
            float h0 = __uint_as_float(hp << 16);
            float h1 = __uint_as_float(hp & 0xFFFF0000u);
            uint32_t lp = bf16x2_rn(f0 - h0, f1 - h1);
            hw[jp] = hp;
            lw[jp] = lp;
            sumF += f0 + f1;
            sumUF = fmaf(u0, f0, fmaf(u1, f1, sumUF));
            if (d == 0) su += u0 + u1;
        }
        outHi[sg] = make_uint4(hw[0], hw[1], hw[2], hw[3]);
        outLo[sg] = make_uint4(lw[0], lw[1], lw[2], lw[3]);
    }

    size_t gb = (size_t)b * GSTRIDE;
    atomicAdd(&g_G[gb + (size_t)256 * 258 + d], sumF);
    atomicAdd(&g_G[gb + (size_t)257 * 258 + d], sumUF);
    if (d == 0) atomicAdd(&g_G[gb + (size_t)257 * 258 + 256], su);
}

// ---------------------------------------------------------------------------
// gram_mma: pipelined (R9/R10 passing version, unchanged)
// ---------------------------------------------------------------------------
#define SROW2 40
#define GMAT (128 * SROW2)

__global__ void __launch_bounds__(256) gram_mma()
{
    extern __shared__ unsigned short sh[];
    int tile = blockIdx.x;
    int b = blockIdx.y;
    int ti = (tile > 0) ? 1 : 0;
    int tj = (tile == 2) ? 1 : 0;
    bool diag = (ti == tj);

    int tid = threadIdx.x;
    int lane = tid & 31;
    int wq = tid >> 5;
    int warp_m = wq >> 2;
    int warp_n = wq & 3;
    int l4 = lane >> 2;
    int lm2 = (lane & 3) * 2;

    const unsigned short* srcs[4];
    srcs[0] = &g_Fhi[((size_t)b * 256 + ti * 128) * 1024];
    srcs[1] = &g_Flo[((size_t)b * 256 + ti * 128) * 1024];
    srcs[2] = &g_Fhi[((size_t)b * 256 + tj * 128) * 1024];
    srcs[3] = &g_Flo[((size_t)b * 256 + tj * 128) * 1024];
    int nmat = diag ? 2 : 4;

    uint32_t base_u32 = smem_u32(sh);

    float d[16][4];
#pragma unroll
    for (int q = 0; q < 16; ++q)
#pragma unroll
        for (int r = 0; r < 4; ++r) d[q][r] = 0.f;

    auto issue = [&](int c, int st) {
        int s0 = c * 32;
        uint32_t stb = base_u32 + (uint32_t)(st * 4 * GMAT * 2);
        for (int mi = 0; mi < nmat; ++mi) {
            uint32_t mb = stb + (uint32_t)(mi * GMAT * 2);
            const unsigned short* src = srcs[mi];
#pragma unroll
            for (int q = 0; q < 2; ++q) {
                int idx = tid + q * 256;
                int r = idx >> 2, cc = idx & 3;
                cpasync16(mb + (uint32_t)(r * SROW2 * 2 + cc * 16),
                          src + (size_t)r * 1024 + s0 + cc * 8);
            }
        }
        cpasync_commit();
    };

    issue(0, 0);
    for (int c = 0; c < 32; ++c) {
        int st = c & 1;
        if (c + 1 < 32) { issue(c + 1, st ^ 1); cpasync_wait1(); }
        else            { cpasync_wait0(); }
        __syncthreads();

        unsigned short* stA = sh + (size_t)st * 4 * GMAT;
        unsigned short* Ahi = stA;
        unsigned short* Alo = stA + GMAT;
        unsigned short* Bhi = diag ? Ahi : stA + 2 * GMAT;
        unsigned short* Blo = diag ? Alo : stA + 3 * GMAT;

#pragma unroll
        for (int ks = 0; ks < 2; ++ks) {
            int k0 = ks * 16;
            uint32_t aH[4][4], aL[4][4], bH[4][2], bL[4][2];
#pragma unroll
            for (int mt = 0; mt < 4; ++mt) {
                int r0 = warp_m * 64 + mt * 16 + l4;
                const unsigned short* p0 = &Ahi[r0 * SROW2 + k0 + lm2];
                const unsigned short* p1 = &Ahi[(r0 + 8) * SROW2 + k0 + lm2];
                aH[mt][0] = *(const uint32_t*)p0;
                aH[mt][1] = *(const uint32_t*)p1;
                aH[mt][2] = *(const uint32_t*)(p0 + 8);
                aH[mt][3] = *(const uint32_t*)(p1 + 8);
                const unsigned short* q0 = &Alo[r0 * SROW2 + k0 + lm2];
                const unsigned short* q1 = &Alo[(r0 + 8) * SROW2 + k0 + lm2];
                aL[mt][0] = *(const uint32_t*)q0;
                aL[mt][1] = *(const uint32_t*)q1;
                aL[mt][2] = *(const uint32_t*)(q0 + 8);
                aL[mt][3] = *(const uint32_t*)(q1 + 8);
            }
#pragma unroll
            for (int nt = 0; nt < 4; ++nt) {
                int n0 = warp_n * 32 + nt * 8 + l4;
                const unsigned short* p = &Bhi[n0 * SROW2 + k0 + lm2];
                bH[nt][0] = *(const uint32_t*)p;
                bH[nt][1] = *(const uint32_t*)(p + 8);
                const unsigned short* q = &Blo[n0 * SROW2 + k0 + lm2];
                bL[nt][0] = *(const uint32_t*)q;
                bL[nt][1] = *(const uint32_t*)(q + 8);
            }
#pragma unroll
            for (int mt = 0; mt < 4; ++mt)
#pragma unroll
                for (int nt = 0; nt < 4; ++nt) {
                    mma16816(d[mt * 4 + nt], aH[mt], bH[nt]);
                    mma16816(d[mt * 4 + nt], aL[mt], bH[nt]);
                    mma16816(d[mt * 4 + nt], aH[mt], bL[nt]);
                }
        }
        __syncthreads();
    }

    size_t gb = (size_t)b * GSTRIDE;
#pragma unroll
    for (int mt = 0; mt < 4; ++mt) {
#pragma unroll
        for (int nt = 0; nt < 4; ++nt) {
            int i0 = ti * 128 + warp_m * 64 + mt * 16 + l4;
            int j0 = tj * 128 + warp_n * 32 + nt * 8 + lm2;
            float* dst0 = &g_G[gb + (size_t)i0 * 258 + j0];
            float* dst1 = &g_G[gb + (size_t)(i0 + 8) * 258 + j0];
            *(float2*)dst0 = make_float2(d[mt * 4 + nt][0], d[mt * 4 + nt][1]);
            *(float2*)dst1 = make_float2(d[mt * 4 + nt][2], d[mt * 4 + nt][3]);
        }
    }
}

// ---------------------------------------------------------------------------
// Phase C: out-of-smem blocked Cholesky (R7 passing version, unchanged)
// ---------------------------------------------------------------------------
#define TRI(i) ((i) * ((i) + 1) / 2)
#define PTS 264
#define BRS 260

__global__ void __launch_bounds__(256, 2) solve_kernel(float* __restrict__ out)
{
    extern __shared__ float sm[];
    float* pan = sm;
    float* Pt  = sm + 8484;
    float* y   = sm + 16932;
    int b = blockIdx.x;
    int tid = threadIdx.x;
    float* A = &g_G[(size_t)b * GSTRIDE];

    for (int j = tid; j < 257; j += 256) y[j] = A[(size_t)257 * 258 + j];

    for (int kb = 0; kb < 256; kb += 32) {
        int Rf = 257 - kb;
        for (int idx = tid; idx < Rf * 32; idx += 256) {
            int r = idx >> 5, c = idx & 31;
            float v = A[(size_t)(kb + r) * 258 + kb + c];
            if (r == c) v += 25.f;
            pan[(kb + r) * 33 + c] = v;
        }
        __syncthreads();
        if (tid < 32) {
            for (int c = 0; c < 32; ++c) {
                float dsq = pan[(kb + c) * 33 + c];
                __syncwarp();
                float dv = sqrtf(dsq);
                if (tid == c) pan[(kb + c) * 33 + c] = dv;
                float lr = 0.f;
                if (tid > c) {
                    lr = pan[(kb + tid) * 33 + c] / dv;
                    pan[(kb + tid) * 33 + c] = lr;
                }
                __syncwarp();
                if (tid > c)
                    for (int c2 = c + 1; c2 <= tid; ++c2)
                        pan[(kb + tid) * 33 + c2] -= lr * pan[(kb + c2) * 33 + c];
                __syncwarp();
            }
        }
        __syncthreads();
        int base = kb + 32;
        int R = 257 - base;
        if (tid < R) {
            int i = base + tid;
            float row[32];
#pragma unroll
            for (int m = 0; m < 32; ++m) row[m] = pan[i * 33 + m];
#pragma unroll
            for (int c = 0; c < 32; ++c) {
                float v = row[c];
#pragma unroll
                for (int m = 0; m < c; ++m) v -= row[m] * pan[(kb + c) * 33 + m];
                row[c] = v / pan[(kb + c) * 33 + c];
            }
#pragma unroll
            for (int m = 0; m < 32; ++m) {
                pan[i * 33 + m] = row[m];
                Pt[m * PTS + tid] = row[m];
            }
        }
        __syncthreads();
        for (int idx = tid; idx < Rf * 32; idx += 256) {
            int r = idx >> 5, c = idx & 31;
            A[(size_t)(kb + r) * 258 + kb + c] = pan[(kb + r) * 33 + c];
        }
        if (R > 0) {
            int Gg = (R + 3) >> 2;
            int nt = Gg * (Gg + 1) / 2;
            for (int tIdx = tid; tIdx < nt; tIdx += 256) {
                int gi = (int)((sqrtf(8.f * tIdx + 1.f) - 1.f) * 0.5f);
                while (TRI(gi + 1) <= tIdx) ++gi;
                while (TRI(gi) > tIdx) --gi;
                int gj = tIdx - TRI(gi);
                int i0 = base + gi * 4, j0 = base + gj * 4;
                unsigned long long acc[4][2];
#pragma unroll
                for (int q = 0; q < 4; ++q) { acc[q][0] = 0ull; acc[q][1] = 0ull; }
#pragma unroll 8
                for (int m = 0; m < 32; ++m) {
                    float4 av = *(const float4*)&Pt[m * PTS + gi * 4];
                    ulonglong2 bv = *(const ulonglong2*)&Pt[m * PTS + gj * 4];
                    unsigned long long s;
                    s = splat2(av.x); fma2(acc[0][0], s, bv.x); fma2(acc[0][1], s, bv.y);
                    s = splat2(av.y); fma2(acc[1][0], s, bv.x); fma2(acc[1][1], s, bv.y);
                    s = splat2(av.z); fma2(acc[2][0], s, bv.x); fma2(acc[2][1], s, bv.y);
                    s = splat2(av.w); fma2(acc[3][0], s, bv.x); fma2(acc[3][1], s, bv.y);
                }
                if (i0 + 3 <= 256 && j0 + 3 <= 256) {
#pragma unroll
                    for (int q = 0; q < 4; ++q) {
                        float* ap = &A[(size_t)(i0 + q) * 258 + j0];
                        float2 o0 = *(float2*)ap;
                        float2 o1 = *(float2*)(ap + 2);
                        float2 v0 = unpk(acc[q][0]);
                        float2 v1 = unpk(acc[q][1]);
                        o0.x -= v0.x; o0.y -= v0.y;
                        o1.x -= v1.x; o1.y -= v1.y;
                        *(float2*)ap = o0;
                        *(float2*)(ap + 2) = o1;
                    }
                } else {
#pragma unroll
                    for (int q = 0; q < 4; ++q) {
                        int i = i0 + q;
                        if (i > 256) continue;
                        float2 v0 = unpk(acc[q][0]);
                        float2 v1 = unpk(acc[q][1]);
                        float vv[4] = {v0.x, v0.y, v1.x, v1.y};
#pragma unroll
                        for (int p = 0; p < 4; ++p) {
                            int j = j0 + p;
                            if (j > 256) continue;
                            A[(size_t)i * 258 + j] -= vv[p];
                        }
                    }
                }
            }
        }
        __syncthreads();
    }
    if (tid == 0)
        A[(size_t)256 * 258 + 256] = sqrtf(A[(size_t)256 * 258 + 256] + 25.f);
    __syncthreads();

    for (int kb = 0; kb < 256; kb += 32) {
        int Rf = 257 - kb;
        for (int idx = tid; idx < Rf * 32; idx += 256) {
            int r = idx >> 5, c = idx & 31;
            pan[(kb + r) * 33 + c] = A[(size_t)(kb + r) * 258 + kb + c];
        }
        __syncthreads();
        if (tid < 32) {
            float acc = y[kb + tid];
#pragma unroll
            for (int m = 0; m < 32; ++m) {
                float dm = pan[(kb + m) * 33 + m];
                if (tid == m) acc /= dm;
                float ym = __shfl_sync(0xffffffffu, acc, m);
                if (tid > m) acc -= pan[(kb + tid) * 33 + m] * ym;
            }
            y[kb + tid] = acc;
        }
        __syncthreads();
        int R = 225 - kb;
        if (tid < R) {
            int i = kb + 32 + tid;
            float acc = y[i];
#pragma unroll
            for (int c = 0; c < 32; ++c) acc -= pan[i * 33 + c] * y[kb + c];
            y[i] = acc;
        }
        __syncthreads();
    }
    if (tid == 0) y[256] /= A[(size_t)256 * 258 + 256];
    __syncthreads();

    if (tid == 0) y[256] /= A[(size_t)256 * 258 + 256];
    __syncthreads();
    {
        float x256 = y[256];
        if (tid < 256) y[tid] -= A[(size_t)256 * 258 + tid] * x256;
        __syncthreads();
    }
    for (int kb = 224; kb >= 0; kb -= 32) {
        for (int idx = tid; idx < 32 * 256; idx += 256) {
            int c = idx >> 8, j = idx & 255;
            pan[c * BRS + j] = A[(size_t)(kb + c) * 258 + j];
        }
        __syncthreads();
        if (tid < 32) {
            float acc = y[kb + tid];
#pragma unroll
            for (int m = 31; m >= 0; --m) {
                float dm = pan[m * BRS + kb + m];
                if (tid == m) acc /= dm;
                float ym = __shfl_sync(0xffffffffu, acc, m);
                if (tid < m) acc -= pan[m * BRS + kb + tid] * ym;
            }
            y[kb + tid] = acc;
        }
        __syncthreads();
        if (tid < kb) {
            float acc = y[tid];
#pragma unroll
            for (int c = 0; c < 32; ++c) acc -= pan[c * BRS + tid] * y[kb + c];
            y[tid] = acc;
        }
        __syncthreads();
    }
    for (int j = tid; j < 257; j += 256) out[b * 257 + j] = y[j];
}

// ---------------------------------------------------------------------------
extern "C" void kernel_launch(void* const* d_in, const int* in_sizes, int n_in,
                              void* d_out, int out_size)
{
    (void)in_sizes; (void)n_in; (void)out_size;
    const float* img = (const float*)d_in[0];
    const float* win = (const float*)d_in[1];
    const float* W1  = (const float*)d_in[2];
    const float* W2  = (const float*)d_in[3];
    float* out = (float*)d_out;

    int solve_smem = 17192 * (int)sizeof(float);
    cudaFuncSetAttribute(solve_kernel, cudaFuncAttributeMaxDynamicSharedMemorySize,
                         solve_smem);
    int gram_smem = 2 * 4 * GMAT * 2;  // 81920 B
    cudaFuncSetAttribute(gram_mma, cudaFuncAttributeMaxDynamicSharedMemorySize, gram_smem);

    esn_persist<<<128, 256>>>(img, win, W1, W2);
    feat_init<<<256, 256>>>();
    feat_kernel<<<dim3(4, 256), 256>>>(img);
    gram_mma<<<dim3(3, 256), 256, gram_smem>>>();
    solve_kernel<<<256, 256, solve_smem>>>(out);
}

// round 12
// speedup vs baseline: 1.3574x; 1.2059x over previous
#include <cuda_runtime.h>
#include <cuda_bf16.h>
#include <cstdint>

// ---------------------------------------------------------------------------
// ESN_2D: B=256, H=W=32, n=128, alpha^2=25, START_T=1
//  Phase A: persistent wavefront; writes bf16 hi/lo features DIRECTLY in
//           [b][s][d] layout + exact fp32 Gram rows 256/257 (feat fused away)
//  Phase B: pipelined mma.sync Gram with ldmatrix.x4.trans fragments
//  Phase C: out-of-smem blocked Cholesky + blocked substitutions
// ---------------------------------------------------------------------------

#define GSTRIDE 66564  // 258*258

__device__ float g_G[(size_t)256 * GSTRIDE];
// bf16 split features, sample-major: [b(256)][s(1024)][d(256)]
__device__ unsigned short g_Fhi[(size_t)256 * 1024 * 256];
__device__ unsigned short g_Flo[(size_t)256 * 1024 * 256];

// ---- packed f32x2 helpers ----
__device__ __forceinline__ unsigned long long splat2(float x) {
    unsigned long long r;
    asm("mov.b64 %0, {%1, %1};" : "=l"(r) : "f"(x));
    return r;
}
__device__ __forceinline__ void fma2(unsigned long long &c, unsigned long long a,
                                     unsigned long long b) {
    asm("fma.rn.f32x2 %0, %1, %2, %0;" : "+l"(c) : "l"(a), "l"(b));
}
__device__ __forceinline__ float2 unpk(unsigned long long v) {
    float2 f;
    asm("mov.b64 {%0, %1}, %2;" : "=f"(f.x), "=f"(f.y) : "l"(v));
    return f;
}

// ---- cp.async helpers ----
__device__ __forceinline__ uint32_t smem_u32(const void* p) {
    uint32_t a;
    asm("{ .reg .u64 t; cvta.to.shared.u64 t, %1; cvt.u32.u64 %0, t; }" : "=r"(a) : "l"(p));
    return a;
}
__device__ __forceinline__ void cpasync16(uint32_t dst, const void* src) {
    asm volatile("cp.async.cg.shared.global [%0], [%1], 16;" :: "r"(dst), "l"(src) : "memory");
}
__device__ __forceinline__ void cpasync_commit() {
    asm volatile("cp.async.commit_group;" ::: "memory");
}
__device__ __forceinline__ void cpasync_wait1() {
    asm volatile("cp.async.wait_group 1;" ::: "memory");
}
__device__ __forceinline__ void cpasync_wait0() {
    asm volatile("cp.async.wait_group 0;" ::: "memory");
}

// ---- bf16 mma.sync + ldmatrix ----
__device__ __forceinline__ void mma16816(float* d, const uint32_t* a, const uint32_t* b) {
    asm volatile(
        "mma.sync.aligned.m16n8k16.row.col.f32.bf16.bf16.f32 "
        "{%0,%1,%2,%3}, {%4,%5,%6,%7}, {%8,%9}, {%0,%1,%2,%3};"
        : "+f"(d[0]), "+f"(d[1]), "+f"(d[2]), "+f"(d[3])
        : "r"(a[0]), "r"(a[1]), "r"(a[2]), "r"(a[3]), "r"(b[0]), "r"(b[1]));
}
__device__ __forceinline__ void ldsm4t(uint32_t& r0, uint32_t& r1, uint32_t& r2,
                                       uint32_t& r3, uint32_t addr) {
    asm volatile("ldmatrix.sync.aligned.m8n8.x4.trans.shared.b16 {%0,%1,%2,%3}, [%4];"
                 : "=r"(r0), "=r"(r1), "=r"(r2), "=r"(r3) : "r"(addr));
}

// fast tanh: 1 - 2/(e^{2x}+1)
__device__ __forceinline__ float fast_tanh(float x) {
    float e = __expf(2.f * x);
    return 1.f - __fdividef(2.f, e + 1.f);
}

// ---------------------------------------------------------------------------
// Phase A: persistent recurrence + fused feature emission.
// 128 CTAs (2 batches each), 256 threads. Thread (rg=t>>7, ri=t&127).
// ---------------------------------------------------------------------------
__global__ void __launch_bounds__(256) esn_persist(const float* __restrict__ img,
                                                   const float* __restrict__ win,
                                                   const float* __restrict__ W1,
                                                   const float* __restrict__ W2)
{
    int b0 = blockIdx.x * 2;
    int t = threadIdx.x;
    int ip = t & 63;
    int jg = t >> 6;

    unsigned long long w1r[32], w2r[32];
#pragma unroll
    for (int m = 0; m < 32; ++m) {
        int j = jg * 32 + m;
        w1r[m] = *(const unsigned long long*)&W1[j * 128 + ip * 2];
        w2r[m] = *(const unsigned long long*)&W2[j * 128 + ip * 2];
    }

    __shared__ float rowbuf[2][32][128];
    __shared__ float lbuf[2][128];
    __shared__ float red[4][2][128];

    for (int idx = t; idx < 2 * 32 * 128; idx += 256)
        ((float*)rowbuf)[idx] = 0.f;

    int rg = t >> 7;
    int ri = t & 127;
    float winv = win[ri];
    const float* imgb = img + (b0 + rg) * 1024;
    size_t fbase = (size_t)(b0 + rg) * 1024 * 256;

    float sumL = 0.f, sumU = 0.f, sumUL = 0.f, sumUU = 0.f, su = 0.f;

    for (int h = 0; h < 32; ++h) {
        lbuf[rg][ri] = 0.f;
        __syncthreads();
        for (int w = 0; w < 32; ++w) {
            int cell = h * 32 + w;
#pragma unroll
            for (int g = 0; g < 2; ++g) {
                unsigned long long accA = 0ull, accB = 0ull;
                const float* lb = &lbuf[g][jg * 32];
                const float* ub = &rowbuf[g][w][jg * 32];
#pragma unroll
                for (int m4 = 0; m4 < 8; ++m4) {
                    float4 lv = *(const float4*)&lb[m4 * 4];
                    float4 uv = *(const float4*)&ub[m4 * 4];
                    fma2(accA, splat2(lv.x), w1r[m4 * 4 + 0]);
                    fma2(accB, splat2(uv.x), w2r[m4 * 4 + 0]);
                    fma2(accA, splat2(lv.y), w1r[m4 * 4 + 1]);
                    fma2(accB, splat2(uv.y), w2r[m4 * 4 + 1]);
                    fma2(accA, splat2(lv.z), w1r[m4 * 4 + 2]);
                    fma2(accB, splat2(uv.z), w2r[m4 * 4 + 2]);
                    fma2(accA, splat2(lv.w), w1r[m4 * 4 + 3]);
                    fma2(accB, splat2(uv.w), w2r[m4 * 4 + 3]);
                }
                float2 a = unpk(accA), bb = unpk(accB);
                *(float2*)&red[jg][g][ip * 2] = make_float2(a.x + bb.x, a.y + bb.y);
            }
            __syncthreads();
            {
                float s = (red[0][rg][ri] + red[1][rg][ri]) +
                          (red[2][rg][ri] + red[3][rg][ri]);
                float x = imgb[cell];
                float v = fast_tanh(fmaf(x, winv, s));
                lbuf[rg][ri] = v;
                rowbuf[rg][w][ri] = v;
                // bf16 hi/lo split once, reused for both feature slots
                unsigned short hs = __bfloat16_as_ushort(__float2bfloat16_rn(v));
                float hf = __uint_as_float(((uint32_t)hs) << 16);
                unsigned short ls = __bfloat16_as_ushort(__float2bfloat16_rn(v - hf));
                if (h >= 1 && w <= 30) {           // left feature d=ri at (h, w+1)
                    size_t o = fbase + (size_t)((h - 1) * 31 + w) * 256 + ri;
                    g_Fhi[o] = hs;
                    g_Flo[o] = ls;
                    float u = imgb[cell + 1];
                    sumL += v;
                    sumUL = fmaf(u, v, sumUL);
                }
                if (w >= 1 && h <= 30) {           // up feature d=128+ri at (h+1, w)
                    size_t o = fbase + (size_t)(h * 31 + (w - 1)) * 256 + 128 + ri;
                    g_Fhi[o] = hs;
                    g_Flo[o] = ls;
                    float u = imgb[cell + 32];
                    sumU += v;
                    sumUU = fmaf(u, v, sumUU);
                }
                if (ri == 0 && h >= 1 && w >= 1) su += x;
            }
            __syncthreads();
        }
    }

    // exact Gram border rows (each thread owns its d slots; no atomics)
    size_t gb = (size_t)(b0 + rg) * GSTRIDE;
    g_G[gb + (size_t)256 * 258 + ri] = sumL;
    g_G[gb + (size_t)256 * 258 + 128 + ri] = sumU;
    g_G[gb + (size_t)257 * 258 + ri] = sumUL;
    g_G[gb + (size_t)257 * 258 + 128 + ri] = sumUU;
    if (ri == 0) {
        g_G[gb + (size_t)256 * 258 + 256] = 961.f;
        g_G[gb + (size_t)257 * 258 + 256] = su;
    }
}

// ---------------------------------------------------------------------------
// gram_mma: [s][d]-layout features, ldmatrix.x4.trans fragments, 2-stage
// cp.async pipeline. Tiles {(0,0),(1,0),(1,1)} of 128x128. grid=(3,256).
// smem: 2 stages * 4 mats * 32 rows * RS(136) shorts = 69632 B.
// ---------------------------------------------------------------------------
#define RSH 136
#define MATSH (32 * RSH)

__global__ void __launch_bounds__(256, 2) gram_mma()
{
    extern __shared__ unsigned short sh[];
    int tile = blockIdx.x;
    int b = blockIdx.y;
    int ti = (tile > 0) ? 1 : 0;
    int tj = (tile == 2) ? 1 : 0;
    bool diag = (ti == tj);

    int tid = threadIdx.x;
    int lane = tid & 31;
    int wq = tid >> 5;
    int warp_m = wq >> 2;
    int warp_n = wq & 3;
    int l4 = lane >> 2;
    int lm2 = (lane & 3) * 2;

    const unsigned short* srcHi = &g_Fhi[(size_t)b * 1024 * 256];
    const unsigned short* srcLo = &g_Flo[(size_t)b * 1024 * 256];
    int dA = ti * 128, dB = tj * 128;

    uint32_t base_u32 = smem_u32(sh);

    // ldmatrix lane address patterns (A: m16k16; B: two n8 tiles per x4)
    int lg = lane >> 3, L8 = lane & 7;
    int a_row = L8 + ((lg >> 1) << 3);
    int a_col = (lg & 1) << 3;
    int b_row = L8 + ((lg & 1) << 3);
    int b_col = (lg >> 1) << 3;

    float d[16][4];
#pragma unroll
    for (int q = 0; q < 16; ++q)
#pragma unroll
        for (int r = 0; r < 4; ++r) d[q][r] = 0.f;

    auto issue = [&](int c, int st) {
        int s0 = c * 32;
        uint32_t stb = base_u32 + (uint32_t)(st * 4 * MATSH * 2);
#pragma unroll
        for (int q = 0; q < 2; ++q) {
            int idx = tid + q * 256;
            int r = idx >> 4, cc = idx & 15;
            size_t srow = (size_t)(s0 + r) * 256;
            uint32_t drow = (uint32_t)(r * RSH * 2 + cc * 16);
            cpasync16(stb + drow, srcHi + srow + dA + cc * 8);
            cpasync16(stb + MATSH * 2 + drow, srcLo + srow + dA + cc * 8);
            if (!diag) {
                cpasync16(stb + 2 * MATSH * 2 + drow, srcHi + srow + dB + cc * 8);
                cpasync16(stb + 3 * MATSH * 2 + drow, srcLo + srow + dB + cc * 8);
            }
        }
        cpasync_commit();
    };

    issue(0, 0);
    for (int c = 0; c < 32; ++c) {
        int st = c & 1;
        if (c + 1 < 32) { issue(c + 1, st ^ 1); cpasync_wait1(); }
        else            { cpasync_wait0(); }
        __syncthreads();

        uint32_t stb = base_u32 + (uint32_t)(st * 4 * MATSH * 2);
        uint32_t mAhi = stb;
        uint32_t mAlo = stb + MATSH * 2;
        uint32_t mBhi = diag ? mAhi : stb + 2 * MATSH * 2;
        uint32_t mBlo = diag ? mAlo : stb + 3 * MATSH * 2;

#pragma unroll
        for (int ks = 0; ks < 2; ++ks) {
            int s0 = ks * 16;
            uint32_t aoff = (uint32_t)(((s0 + a_row) * RSH + a_col) * 2);
            uint32_t boff = (uint32_t)(((s0 + b_row) * RSH + b_col) * 2);

            uint32_t aH[4][4], aL[4][4], bH[4][2], bL[4][2];
#pragma unroll
            for (int mt = 0; mt < 4; ++mt) {
                uint32_t dcol = (uint32_t)((warp_m * 64 + mt * 16) * 2);
                ldsm4t(aH[mt][0], aH[mt][1], aH[mt][2], aH[mt][3], mAhi + aoff + dcol);
                ldsm4t(aL[mt][0], aL[mt][1], aL[mt][2], aL[mt][3], mAlo + aoff + dcol);
            }
#pragma unroll
            for (int pp = 0; pp < 2; ++pp) {
                uint32_t ecol = (uint32_t)((warp_n * 32 + pp * 16) * 2);
                ldsm4t(bH[2 * pp][0], bH[2 * pp][1], bH[2 * pp + 1][0], bH[2 * pp + 1][1],
                       mBhi + boff + ecol);
                ldsm4t(bL[2 * pp][0], bL[2 * pp][1], bL[2 * pp + 1][0], bL[2 * pp + 1][1],
                       mBlo + boff + ecol);
            }
#pragma unroll
            for (int mt = 0; mt < 4; ++mt)
#pragma unroll
                for (int nt = 0; nt < 4; ++nt) {
                    mma16816(d[mt * 4 + nt], aH[mt], bH[nt]);
                    mma16816(d[mt * 4 + nt], aL[mt], bH[nt]);
                    mma16816(d[mt * 4 + nt], aH[mt], bL[nt]);
                }
        }
        __syncthreads();
    }

    size_t gb = (size_t)b * GSTRIDE;
#pragma unroll
    for (int mt = 0; mt < 4; ++mt) {
#pragma unroll
        for (int nt = 0; nt < 4; ++nt) {
            int i0 = ti * 128 + warp_m * 64 + mt * 16 + l4;
            int j0 = tj * 128 + warp_n * 32 + nt * 8 + lm2;
            float* dst0 = &g_G[gb + (size_t)i0 * 258 + j0];
            float* dst1 = &g_G[gb + (size_t)(i0 + 8) * 258 + j0];
            *(float2*)dst0 = make_float2(d[mt * 4 + nt][0], d[mt * 4 + nt][1]);
            *(float2*)dst1 = make_float2(d[mt * 4 + nt][2], d[mt * 4 + nt][3]);
        }
    }
}

// ---------------------------------------------------------------------------
// Phase C: out-of-smem blocked Cholesky (R7 passing version, unchanged)
// ---------------------------------------------------------------------------
#define TRI(i) ((i) * ((i) + 1) / 2)
#define PTS 264
#define BRS 260

__global__ void __launch_bounds__(256, 2) solve_kernel(float* __restrict__ out)
{
    extern __shared__ float sm[];
    float* pan = sm;
    float* Pt  = sm + 8484;
    float* y   = sm + 16932;
    int b = blockIdx.x;
    int tid = threadIdx.x;
    float* A = &g_G[(size_t)b * GSTRIDE];

    for (int j = tid; j < 257; j += 256) y[j] = A[(size_t)257 * 258 + j];

    for (int kb = 0; kb < 256; kb += 32) {
        int Rf = 257 - kb;
        for (int idx = tid; idx < Rf * 32; idx += 256) {
            int r = idx >> 5, c = idx & 31;
            float v = A[(size_t)(kb + r) * 258 + kb + c];
            if (r == c) v += 25.f;
            pan[(kb + r) * 33 + c] = v;
        }
        __syncthreads();
        if (tid < 32) {
            for (int c = 0; c < 32; ++c) {
                float dsq = pan[(kb + c) * 33 + c];
                __syncwarp();
                float dv = sqrtf(dsq);
                if (tid == c) pan[(kb + c) * 33 + c] = dv;
                float lr = 0.f;
                if (tid > c) {
                    lr = pan[(kb + tid) * 33 + c] / dv;
                    pan[(kb + tid) * 33 + c] = lr;
                }
                __syncwarp();
                if (tid > c)
                    for (int c2 = c + 1; c2 <= tid; ++c2)
                        pan[(kb + tid) * 33 + c2] -= lr * pan[(kb + c2) * 33 + c];
                __syncwarp();
            }
        }
        __syncthreads();
        int base = kb + 32;
        int R = 257 - base;
        if (tid < R) {
            int i = base + tid;
            float row[32];
#pragma unroll
            for (int m = 0; m < 32; ++m) row[m] = pan[i * 33 + m];
#pragma unroll
            for (int c = 0; c < 32; ++c) {
                float v = row[c];
#pragma unroll
                for (int m = 0; m < c; ++m) v -= row[m] * pan[(kb + c) * 33 + m];
                row[c] = v / pan[(kb + c) * 33 + c];
            }
#pragma unroll
            for (int m = 0; m < 32; ++m) {
                pan[i * 33 + m] = row[m];
                Pt[m * PTS + tid] = row[m];
            }
        }
        __syncthreads();
        for (int idx = tid; idx < Rf * 32; idx += 256) {
            int r = idx >> 5, c = idx & 31;
            A[(size_t)(kb + r) * 258 + kb + c] = pan[(kb + r) * 33 + c];
        }
        if (R > 0) {
            int Gg = (R + 3) >> 2;
            int nt = Gg * (Gg + 1) / 2;
            for (int tIdx = tid; tIdx < nt; tIdx += 256) {
                int gi = (int)((sqrtf(8.f * tIdx + 1.f) - 1.f) * 0.5f);
                while (TRI(gi + 1) <= tIdx) ++gi;
                while (TRI(gi) > tIdx) --gi;
                int gj = tIdx - TRI(gi);
                int i0 = base + gi * 4, j0 = base + gj * 4;
                unsigned long long acc[4][2];
#pragma unroll
                for (int q = 0; q < 4; ++q) { acc[q][0] = 0ull; acc[q][1] = 0ull; }
#pragma unroll 8
                for (int m = 0; m < 32; ++m) {
                    float4 av = *(const float4*)&Pt[m * PTS + gi * 4];
                    ulonglong2 bv = *(const ulonglong2*)&Pt[m * PTS + gj * 4];
                    unsigned long long s;
                    s = splat2(av.x); fma2(acc[0][0], s, bv.x); fma2(acc[0][1], s, bv.y);
                    s = splat2(av.y); fma2(acc[1][0], s, bv.x); fma2(acc[1][1], s, bv.y);
                    s = splat2(av.z); fma2(acc[2][0], s, bv.x); fma2(acc[2][1], s, bv.y);
                    s = splat2(av.w); fma2(acc[3][0], s, bv.x); fma2(acc[3][1], s, bv.y);
                }
                if (i0 + 3 <= 256 && j0 + 3 <= 256) {
#pragma unroll
                    for (int q = 0; q < 4; ++q) {
                        float* ap = &A[(size_t)(i0 + q) * 258 + j0];
                        float2 o0 = *(float2*)ap;
                        float2 o1 = *(float2*)(ap + 2);
                        float2 v0 = unpk(acc[q][0]);
                        float2 v1 = unpk(acc[q][1]);
                        o0.x -= v0.x; o0.y -= v0.y;
                        o1.x -= v1.x; o1.y -= v1.y;
                        *(float2*)ap = o0;
                        *(float2*)(ap + 2) = o1;
                    }
                } else {
#pragma unroll
                    for (int q = 0; q < 4; ++q) {
                        int i = i0 + q;
                        if (i > 256) continue;
                        float2 v0 = unpk(acc[q][0]);
                        float2 v1 = unpk(acc[q][1]);
                        float vv[4] = {v0.x, v0.y, v1.x, v1.y};
#pragma unroll
                        for (int p = 0; p < 4; ++p) {
                            int j = j0 + p;
                            if (j > 256) continue;
                            A[(size_t)i * 258 + j] -= vv[p];
                        }
                    }
                }
            }
        }
        __syncthreads();
    }
    if (tid == 0)
        A[(size_t)256 * 258 + 256] = sqrtf(A[(size_t)256 * 258 + 256] + 25.f);
    __syncthreads();

    for (int kb = 0; kb < 256; kb += 32) {
        int Rf = 257 - kb;
        for (int idx = tid; idx < Rf * 32; idx += 256) {
            int r = idx >> 5, c = idx & 31;
            pan[(kb + r) * 33 + c] = A[(size_t)(kb + r) * 258 + kb + c];
        }
        __syncthreads();
        if (tid < 32) {
            float acc = y[kb + tid];
#pragma unroll
            for (int m = 0; m < 32; ++m) {
                float dm = pan[(kb + m) * 33 + m];
                if (tid == m) acc /= dm;
                float ym = __shfl_sync(0xffffffffu, acc, m);
                if (tid > m) acc -= pan[(kb + tid) * 33 + m] * ym;
            }
            y[kb + tid] = acc;
        }
        __syncthreads();
        int R = 225 - kb;
        if (tid < R) {
            int i = kb + 32 + tid;
            float acc = y[i];
#pragma unroll
            for (int c = 0; c < 32; ++c) acc -= pan[i * 33 + c] * y[kb + c];
            y[i] = acc;
        }
        __syncthreads();
    }
    if (tid == 0) y[256] /= A[(size_t)256 * 258 + 256];
    __syncthreads();

    if (tid == 0) y[256] /= A[(size_t)256 * 258 + 256];
    __syncthreads();
    {
        float x256 = y[256];
        if (tid < 256) y[tid] -= A[(size_t)256 * 258 + tid] * x256;
        __syncthreads();
    }
    for (int kb = 224; kb >= 0; kb -= 32) {
        for (int idx = tid; idx < 32 * 256; idx += 256) {
            int c = idx >> 8, j = idx & 255;
            pan[c * BRS + j] = A[(size_t)(kb + c) * 258 + j];
        }
        __syncthreads();
        if (tid < 32) {
            float acc = y[kb + tid];
#pragma unroll
            for (int m = 31; m >= 0; --m) {
                float dm = pan[m * BRS + kb + m];
                if (tid == m) acc /= dm;
                float ym = __shfl_sync(0xffffffffu, acc, m);
                if (tid < m) acc -= pan[m * BRS + kb + tid] * ym;
            }
            y[kb + tid] = acc;
        }
        __syncthreads();
        if (tid < kb) {
            float acc = y[tid];
#pragma unroll
            for (int c = 0; c < 32; ++c) acc -= pan[c * BRS + tid] * y[kb + c];
            y[tid] = acc;
        }
        __syncthreads();
    }
    for (int j = tid; j < 257; j += 256) out[b * 257 + j] = y[j];
}

// ---------------------------------------------------------------------------
extern "C" void kernel_launch(void* const* d_in, const int* in_sizes, int n_in,
                              void* d_out, int out_size)
{
    (void)in_sizes; (void)n_in; (void)out_size;
    const float* img = (const float*)d_in[0];
    const float* win = (const float*)d_in[1];
    const float* W1  = (const float*)d_in[2];
    const float* W2  = (const float*)d_in[3];
    float* out = (float*)d_out;

    int solve_smem = 17192 * (int)sizeof(float);
    cudaFuncSetAttribute(solve_kernel, cudaFuncAttributeMaxDynamicSharedMemorySize,
                         solve_smem);
    int gram_smem = 2 * 4 * MATSH * 2;  // 69632 B
    cudaFuncSetAttribute(gram_mma, cudaFuncAttributeMaxDynamicSharedMemorySize, gram_smem);

    esn_persist<<<128, 256>>>(img, win, W1, W2);
    gram_mma<<<dim3(3, 256), 256, gram_smem>>>();
    solve_kernel<<<256, 256, solve_smem>>>(out);
}